// round 1
// baseline (speedup 1.0000x reference)
#include <cuda_runtime.h>
#include <cstdint>

// Problem: B=4096, D=2048, C=16384, topk=64 (dims read from in_sizes at launch).
// recon = TopK(BN(x @ W_enc^T)) @ normalize_cols(W_dec)^T + b_dec
// b_enc is mathematically cancelled by batch-norm mean subtraction -> skipped.

#define MAX_B 4096
#define MAX_C 16384
#define MAX_D 2048

// Scratch (static __device__ globals; no cudaMalloc allowed)
__device__ float g_h[(size_t)MAX_B * MAX_C];       // 256 MB: encoder pre-BN activations
__device__ float g_WnT[(size_t)MAX_C * MAX_D];     // 128 MB: normalized decoder, row-major [C,D]
__device__ float g_inv_norm[MAX_C];
__device__ float g_scale[MAX_C];                   // gamma * rsqrt(var+eps)
__device__ float g_bias[MAX_C];                    // beta - mean*scale

// ---------------------------------------------------------------------------
// 1) W_dec column inv-norms (fp64 accumulation, 4-way ILP)
// ---------------------------------------------------------------------------
__global__ void colnorm_kernel(const float* __restrict__ Wdec, int D, int C) {
    int c = blockIdx.x * blockDim.x + threadIdx.x;
    if (c >= C) return;
    double s0 = 0.0, s1 = 0.0, s2 = 0.0, s3 = 0.0;
    int d = 0;
    for (; d + 3 < D; d += 4) {
        float w0 = Wdec[(size_t)(d + 0) * C + c];
        float w1 = Wdec[(size_t)(d + 1) * C + c];
        float w2 = Wdec[(size_t)(d + 2) * C + c];
        float w3 = Wdec[(size_t)(d + 3) * C + c];
        s0 += (double)w0 * w0; s1 += (double)w1 * w1;
        s2 += (double)w2 * w2; s3 += (double)w3 * w3;
    }
    for (; d < D; d++) { float w = Wdec[(size_t)d * C + c]; s0 += (double)w * w; }
    double n = sqrt(s0 + s1 + s2 + s3);
    if (n < 1e-12) n = 1e-12;
    g_inv_norm[c] = (float)(1.0 / n);
}

// ---------------------------------------------------------------------------
// 2) Transpose + scale: WnT[c,d] = W_dec[d,c] * inv_norm[c]
// ---------------------------------------------------------------------------
__global__ void transpose_kernel(const float* __restrict__ Wdec, int D, int C) {
    __shared__ float tile[32][33];
    int c0 = blockIdx.x * 32, d0 = blockIdx.y * 32;
    for (int i = threadIdx.y; i < 32; i += 8) {
        int d = d0 + i, c = c0 + threadIdx.x;
        tile[i][threadIdx.x] = (d < D && c < C) ? Wdec[(size_t)d * C + c] : 0.f;
    }
    __syncthreads();
    for (int i = threadIdx.y; i < 32; i += 8) {
        int c = c0 + i, d = d0 + threadIdx.x;
        if (c < C && d < D)
            g_WnT[(size_t)c * D + d] = tile[threadIdx.x][i] * g_inv_norm[c];
    }
}

// ---------------------------------------------------------------------------
// 3) fp32 SGEMM: h[m,n] = sum_k x[m,k] * W_enc[n,k]   (both K-major)
//    128x128 block tile, BK=16, 256 threads, 8x8 per thread.
// ---------------------------------------------------------------------------
__global__ __launch_bounds__(256) void gemm_kernel(
    const float* __restrict__ A,   // x      [M,K]
    const float* __restrict__ Bm,  // W_enc  [N,K]
    int M, int N, int K)
{
    const int BK = 16;
    __shared__ float As[16][132];
    __shared__ float Bs[16][132];

    int tid = threadIdx.x;
    int tx = tid & 15;         // 0..15 -> N micro
    int ty = tid >> 4;         // 0..15 -> M micro
    int m0 = blockIdx.y * 128;
    int n0 = blockIdx.x * 128;

    float acc[8][8];
#pragma unroll
    for (int i = 0; i < 8; i++)
#pragma unroll
        for (int j = 0; j < 8; j++) acc[i][j] = 0.f;

    for (int k0 = 0; k0 < K; k0 += BK) {
#pragma unroll
        for (int l = 0; l < 2; l++) {
            int idx = tid + l * 256;       // 0..511
            int row = idx >> 2;            // 0..127
            int kq  = (idx & 3) * 4;       // 0,4,8,12
            int gm = m0 + row; if (gm > M - 1) gm = M - 1;
            int gn = n0 + row; if (gn > N - 1) gn = N - 1;
            float4 av = *(const float4*)(A  + (size_t)gm * K + k0 + kq);
            float4 bv = *(const float4*)(Bm + (size_t)gn * K + k0 + kq);
            As[kq + 0][row] = av.x; As[kq + 1][row] = av.y;
            As[kq + 2][row] = av.z; As[kq + 3][row] = av.w;
            Bs[kq + 0][row] = bv.x; Bs[kq + 1][row] = bv.y;
            Bs[kq + 2][row] = bv.z; Bs[kq + 3][row] = bv.w;
        }
        __syncthreads();
#pragma unroll
        for (int kk = 0; kk < BK; kk++) {
            float a[8], b[8];
#pragma unroll
            for (int i = 0; i < 8; i++) a[i] = As[kk][ty * 8 + i];
#pragma unroll
            for (int j = 0; j < 8; j++) b[j] = Bs[kk][tx * 8 + j];
#pragma unroll
            for (int i = 0; i < 8; i++)
#pragma unroll
                for (int j = 0; j < 8; j++) acc[i][j] += a[i] * b[j];
        }
        __syncthreads();
    }

#pragma unroll
    for (int i = 0; i < 8; i++) {
        int m = m0 + ty * 8 + i;
        if (m >= M) continue;
#pragma unroll
        for (int j = 0; j < 8; j++) {
            int n = n0 + tx * 8 + j;
            if (n < N) g_h[(size_t)m * N + n] = acc[i][j];
        }
    }
}

// ---------------------------------------------------------------------------
// 4) Column stats (fp64 accumulation) -> fused BN scale/bias
// ---------------------------------------------------------------------------
__global__ void stats_kernel(const float* __restrict__ gamma,
                             const float* __restrict__ beta,
                             int Bsz, int C)
{
    int c = blockIdx.x * blockDim.x + threadIdx.x;
    if (c >= C) return;
    double s0 = 0, s1 = 0, s2 = 0, s3 = 0;
    double q0 = 0, q1 = 0, q2 = 0, q3 = 0;
    int b = 0;
    for (; b + 3 < Bsz; b += 4) {
        float v0 = g_h[(size_t)(b + 0) * C + c];
        float v1 = g_h[(size_t)(b + 1) * C + c];
        float v2 = g_h[(size_t)(b + 2) * C + c];
        float v3 = g_h[(size_t)(b + 3) * C + c];
        s0 += v0; s1 += v1; s2 += v2; s3 += v3;
        q0 += (double)v0 * v0; q1 += (double)v1 * v1;
        q2 += (double)v2 * v2; q3 += (double)v3 * v3;
    }
    for (; b < Bsz; b++) { float v = g_h[(size_t)b * C + c]; s0 += v; q0 += (double)v * v; }
    double mean = (s0 + s1 + s2 + s3) / (double)Bsz;
    double var  = (q0 + q1 + q2 + q3) / (double)Bsz - mean * mean;
    double inv  = 1.0 / sqrt(var + 1e-5);
    float sc = (float)((double)gamma[c] * inv);
    g_scale[c] = sc;
    g_bias[c]  = beta[c] - (float)(mean) * sc;
}

// ---------------------------------------------------------------------------
// 5) Per-row: BN+ReLU -> exact radix top-k threshold -> sparse decode
//    One block (256 threads) per row. Row cached in dynamic smem.
// ---------------------------------------------------------------------------
__global__ __launch_bounds__(256) void topk_decode_kernel(
    const float* __restrict__ b_dec,
    const int*   __restrict__ topk_p,
    float* __restrict__ out,
    int Bsz, int C, int D)
{
    extern __shared__ float sm[];
    float*    vals   = sm;                                   // C floats
    unsigned* hist   = (unsigned*)(vals + C);                // 2048
    unsigned* chunks = hist + 2048;                          // 256

    __shared__ int   s_selIdx[1024];
    __shared__ float s_selVal[1024];
    __shared__ int   s_eqIdx[256];
    __shared__ int s_nsel, s_neq, s_need, s_chunk, s_flagzero;
    __shared__ unsigned s_prefix;

    int row = blockIdx.x;
    int tid = threadIdx.x;
    int k = *topk_p;
    if (k > C) k = C;
    if (k > 1024) k = 1024;

    // BN + ReLU into smem (force +0.0 so key==0 <=> value==0)
    for (int c = tid; c < C; c += 256) {
        float v = g_h[(size_t)row * C + c];
        v = v * g_scale[c] + g_bias[c];
        vals[c] = (v > 0.f) ? v : 0.f;
    }
    if (tid == 0) { s_nsel = 0; s_neq = 0; s_need = k; s_prefix = 0u; s_flagzero = 0; }
    __syncthreads();

    if (k > 0) {
        const int      shifts[3]  = {21, 10, 0};
        const int      nbitsA[3]  = {11, 11, 10};
        const unsigned maskHi[3]  = {0u, 0xFFE00000u, 0xFFFFFC00u};

        for (int r = 0; r < 3; r++) {
            int nb = 1 << nbitsA[r];
            for (int i = tid; i < nb; i += 256) hist[i] = 0u;
            __syncthreads();

            unsigned pre = s_prefix, mh = maskHi[r], msk = (unsigned)(nb - 1);
            int sh = shifts[r];
            for (int c = tid; c < C; c += 256) {
                unsigned key = __float_as_uint(vals[c]);
                if (key != 0u && (key & mh) == pre)
                    atomicAdd(&hist[(key >> sh) & msk], 1u);
            }
            __syncthreads();

            // chunk sums (8 bins/chunk) + inclusive suffix scan
            int NCH = nb >> 3;
            unsigned csum = 0u;
            if (tid < NCH) {
#pragma unroll
                for (int j = 0; j < 8; j++) csum += hist[tid * 8 + j];
                chunks[tid] = csum;
            }
            __syncthreads();
            for (int off = 1; off < NCH; off <<= 1) {
                unsigned add = 0u;
                if (tid < NCH && tid + off < NCH) add = chunks[tid + off];
                __syncthreads();
                if (tid < NCH) chunks[tid] += add;
                __syncthreads();
            }

            int need = s_need;
            if (tid < NCH) {
                int incl = (int)chunks[tid];
                int excl = incl - (int)csum;
                if (excl < need && incl >= need) s_chunk = tid;
                if (tid == 0 && incl < need) s_flagzero = 1; // fewer positives than k
            }
            __syncthreads();
            if (s_flagzero) break;

            if (tid == 0) {
                int t = s_chunk;
                unsigned cs = 0u;
#pragma unroll
                for (int j = 0; j < 8; j++) cs += hist[t * 8 + j];
                int cum = (int)chunks[t] - (int)cs;  // exclusive suffix
                for (int j = 7; j >= 0; j--) {
                    int hc = (int)hist[t * 8 + j];
                    cum += hc;
                    if (cum >= need) {
                        s_prefix |= ((unsigned)(t * 8 + j)) << sh;
                        s_need = need - (cum - hc);
                        break;
                    }
                }
            }
            __syncthreads();
        }
        __syncthreads();

        unsigned T = s_prefix;
        int need_eq = s_need;
        bool zeroThresh = (s_flagzero != 0);

        // Selection pass
        for (int c = tid; c < C; c += 256) {
            unsigned key = __float_as_uint(vals[c]);
            if (key == 0u) continue;
            if (zeroThresh || key > T) {
                int p = atomicAdd(&s_nsel, 1);
                if (p < 1024) { s_selIdx[p] = c; s_selVal[p] = vals[c]; }
            } else if (key == T) {
                int p = atomicAdd(&s_neq, 1);
                if (p < 256) s_eqIdx[p] = c;
            }
        }
        __syncthreads();

        // Tie handling: lowest indices first (matches lax.top_k ordering semantics)
        if (!zeroThresh && tid == 0) {
            int ne = s_neq; if (ne > 256) ne = 256;
            for (int i = 1; i < ne; i++) {
                int v = s_eqIdx[i]; int j = i - 1;
                while (j >= 0 && s_eqIdx[j] > v) { s_eqIdx[j + 1] = s_eqIdx[j]; j--; }
                s_eqIdx[j + 1] = v;
            }
            int take = need_eq; if (take > ne) take = ne;
            int base = s_nsel;
            for (int i = 0; i < take; i++) {
                int p = base + i;
                if (p < 1024) { s_selIdx[p] = s_eqIdx[i]; s_selVal[p] = __uint_as_float(T); }
            }
            s_nsel = base + take;
        }
        __syncthreads();
    }

    int nsel = s_nsel; if (nsel > 1024) nsel = 1024;

    // Sparse decode: recon[row, :] = sum_j val_j * WnT[idx_j, :] + b_dec
    for (int dbase = 0; dbase < D; dbase += 1024) {
        int d = dbase + tid * 4;
        if (d + 3 < D) {
            float4 acc = *(const float4*)(b_dec + d);
            for (int j = 0; j < nsel; j++) {
                int   ci = s_selIdx[j];
                float v  = s_selVal[j];
                float4 w = *(const float4*)(&g_WnT[(size_t)ci * D + d]);
                acc.x += v * w.x; acc.y += v * w.y;
                acc.z += v * w.z; acc.w += v * w.w;
            }
            *(float4*)(out + (size_t)row * D + d) = acc;
        } else {
            for (int dd = d; dd < D && dd < dbase + 1024 + tid * 4 + 4; dd++) {
                if (dd < dbase || dd >= dbase + 1024) break;
                float acc = b_dec[dd];
                for (int j = 0; j < nsel; j++)
                    acc += s_selVal[j] * g_WnT[(size_t)s_selIdx[j] * D + dd];
                out[(size_t)row * D + dd] = acc;
            }
        }
    }
}

// ---------------------------------------------------------------------------
// Launch
// ---------------------------------------------------------------------------
extern "C" void kernel_launch(void* const* d_in, const int* in_sizes, int n_in,
                              void* d_out, int out_size)
{
    const float* x     = (const float*)d_in[0];
    const float* W_enc = (const float*)d_in[1];
    // d_in[2] = b_enc : cancelled by batch norm, unused
    const float* gamma = (const float*)d_in[3];
    const float* beta  = (const float*)d_in[4];
    const float* W_dec = (const float*)d_in[5];
    const float* b_dec = (const float*)d_in[6];
    const int*   topk  = (const int*)d_in[7];

    int D = in_sizes[6];          // b_dec size
    int C = in_sizes[2];          // b_enc size
    int B = in_sizes[0] / D;      // x elements / D
    float* out = (float*)d_out;

    colnorm_kernel<<<(C + 255) / 256, 256>>>(W_dec, D, C);

    dim3 tg((C + 31) / 32, (D + 31) / 32);
    transpose_kernel<<<tg, dim3(32, 8)>>>(W_dec, D, C);

    dim3 gg((C + 127) / 128, (B + 127) / 128);
    gemm_kernel<<<gg, 256>>>(x, W_enc, B, C, D);

    stats_kernel<<<(C + 255) / 256, 256>>>(gamma, beta, B, C);

    size_t dyn = (size_t)C * sizeof(float) + 2048 * sizeof(unsigned) + 256 * sizeof(unsigned);
    cudaFuncSetAttribute(topk_decode_kernel,
                         cudaFuncAttributeMaxDynamicSharedMemorySize, (int)dyn);
    topk_decode_kernel<<<B, 256, dyn>>>(b_dec, topk, out, B, C, D);
}

// round 4
// speedup vs baseline: 1.2211x; 1.2211x over previous
#include <cuda_runtime.h>
#include <cuda_fp16.h>
#include <cstdint>

// B=4096, D(K)=2048, C=16384, topk=64
// recon = TopK(BN(x @ W_enc^T)) @ normalize_cols(W_dec)^T + b_dec
// b_enc cancels inside batch-norm -> skipped everywhere (consistent).
//
// Strategy: approximate h via split-fp16 HMMA GEMM (error ~2e-6, only used for
// BN batch stats and candidate generation with margin 32), then recompute the
// top-96 candidate activations per row with a serial ascending-k FFMA fp32
// chain (bit-matching the R1 kernel that passed), exact rank, top-k, decode.

#define MAX_B 4096
#define MAX_C 16384
#define MAX_D 2048
#define NSPLIT 32
#define NCAND 160

__device__ float g_h[(size_t)MAX_B * MAX_C];        // 256 MB approx pre-BN activations
__device__ float g_WnT[(size_t)MAX_C * MAX_D];      // 128 MB normalized decoder [C,D]
__device__ float g_inv_norm[MAX_C];
__device__ float g_scale[MAX_C];
__device__ float g_bias[MAX_C];
__device__ double g_psum[NSPLIT * MAX_C];
__device__ double g_psumsq[NSPLIT * MAX_C];
__device__ __half g_xh[(size_t)MAX_B * MAX_D];
__device__ __half g_xl[(size_t)MAX_B * MAX_D];
__device__ __half g_wh[(size_t)MAX_C * MAX_D];
__device__ __half g_wl[(size_t)MAX_C * MAX_D];

// ---------------------------------------------------------------------------
// fp16 split kernels (power-of-2 pre-scaling keeps residuals normal-range)
// ---------------------------------------------------------------------------
__global__ void split_x_kernel(const float* __restrict__ src, int n) {
    int i = blockIdx.x * blockDim.x + threadIdx.x;
    if (i >= n) return;
    float s = src[i] * 4096.0f;                  // 2^12, exact
    __half h = __float2half_rn(s);
    g_xh[i] = h;
    g_xl[i] = __float2half_rn(s - __half2float(h));
}
__global__ void split_w_kernel(const float* __restrict__ src, int n) {
    int i = blockIdx.x * blockDim.x + threadIdx.x;
    if (i >= n) return;
    float s = src[i] * 262144.0f;                // 2^18, exact
    __half h = __float2half_rn(s);
    g_wh[i] = h;
    g_wl[i] = __float2half_rn(s - __half2float(h));
}

// ---------------------------------------------------------------------------
// W_dec column inv-norms (fp64)
// ---------------------------------------------------------------------------
__global__ void colnorm_kernel(const float* __restrict__ Wdec, int D, int C) {
    int c = blockIdx.x * blockDim.x + threadIdx.x;
    if (c >= C) return;
    double s0 = 0, s1 = 0, s2 = 0, s3 = 0;
    int d = 0;
    for (; d + 3 < D; d += 4) {
        float w0 = Wdec[(size_t)(d + 0) * C + c];
        float w1 = Wdec[(size_t)(d + 1) * C + c];
        float w2 = Wdec[(size_t)(d + 2) * C + c];
        float w3 = Wdec[(size_t)(d + 3) * C + c];
        s0 += (double)w0 * w0; s1 += (double)w1 * w1;
        s2 += (double)w2 * w2; s3 += (double)w3 * w3;
    }
    for (; d < D; d++) { float w = Wdec[(size_t)d * C + c]; s0 += (double)w * w; }
    double n = sqrt(s0 + s1 + s2 + s3);
    if (n < 1e-12) n = 1e-12;
    g_inv_norm[c] = (float)(1.0 / n);
}

// ---------------------------------------------------------------------------
// Transpose + scale: WnT[c,d] = W_dec[d,c] * inv_norm[c]
// ---------------------------------------------------------------------------
__global__ void transpose_kernel(const float* __restrict__ Wdec, int D, int C) {
    __shared__ float tile[32][33];
    int c0 = blockIdx.x * 32, d0 = blockIdx.y * 32;
    for (int i = threadIdx.y; i < 32; i += 8) {
        int d = d0 + i, c = c0 + threadIdx.x;
        tile[i][threadIdx.x] = (d < D && c < C) ? Wdec[(size_t)d * C + c] : 0.f;
    }
    __syncthreads();
    for (int i = threadIdx.y; i < 32; i += 8) {
        int c = c0 + i, d = d0 + threadIdx.x;
        if (c < C && d < D)
            g_WnT[(size_t)c * D + d] = tile[threadIdx.x][i] * g_inv_norm[c];
    }
}

// ---------------------------------------------------------------------------
// mma.sync split-fp16 GEMM (approx h): 128x128 tile, BK=64, 3-stage cp.async
// ---------------------------------------------------------------------------
#define BKH 64
#define STAGE_BYTES 65536        // 4 matrices x 128 x 64 halves x 2B
#define STAGES 3
#define GEMM_SMEM (STAGES * STAGE_BYTES)

#define LDSM4(R0, R1, R2, R3, ADDR) \
    asm volatile("ldmatrix.sync.aligned.m8n8.x4.shared.b16 {%0,%1,%2,%3}, [%4];" \
                 : "=r"(R0), "=r"(R1), "=r"(R2), "=r"(R3) : "r"(ADDR))

#define MMA16816(CC, A0, A1, A2, A3, B0, B1) \
    asm volatile("mma.sync.aligned.m16n8k16.row.col.f32.f16.f16.f32 " \
                 "{%0,%1,%2,%3}, {%4,%5,%6,%7}, {%8,%9}, {%0,%1,%2,%3};" \
                 : "+f"((CC)[0]), "+f"((CC)[1]), "+f"((CC)[2]), "+f"((CC)[3]) \
                 : "r"(A0), "r"(A1), "r"(A2), "r"(A3), "r"(B0), "r"(B1))

__device__ __forceinline__ uint32_t smem_u32(const void* p) {
    uint32_t a;
    asm("{ .reg .u64 t; cvta.to.shared.u64 t, %1; cvt.u32.u64 %0, t; }" : "=r"(a) : "l"(p));
    return a;
}
__device__ __forceinline__ uint32_t swz(uint32_t base, int row, int kbyte) {
    return base + row * 128 + ((((kbyte >> 4) ^ row) & 7) << 4);
}
__device__ __forceinline__ void cpasync16(uint32_t sa, const void* g) {
    asm volatile("cp.async.cg.shared.global [%0], [%1], 16;" :: "r"(sa), "l"(g));
}

__device__ __forceinline__ void load_stage(uint32_t sbase, int m0, int n0,
                                           int k0, int K, int tid) {
    const __half* srcs[4] = {g_xh, g_xl, g_wh, g_wl};
    int r0s[4] = {m0, m0, n0, n0};
#pragma unroll
    for (int mat = 0; mat < 4; mat++) {
        const __half* src = srcs[mat];
        int r0 = r0s[mat];
#pragma unroll
        for (int s = 0; s < 4; s++) {
            int idx = tid * 4 + s;             // 0..1023
            int row = idx >> 3, seg = idx & 7;
            const __half* g = src + (size_t)(r0 + row) * K + k0 + seg * 8;
            cpasync16(swz(sbase + mat * 16384, row, seg * 16), g);
        }
    }
}

__global__ __launch_bounds__(256, 1)
void hgemm_kernel(int M, int N, int K) {
    extern __shared__ __align__(1024) char smem[];
    const uint32_t sb = smem_u32(smem);
    const int tid = threadIdx.x;
    const int wid = tid >> 5, lane = tid & 31;
    const int wm = (wid & 1) * 64;      // warp tile 64 (M) x 32 (N)
    const int wn = (wid >> 1) * 32;
    const int m0 = blockIdx.x * 128;
    const int n0 = blockIdx.y * 128;
    const int grp = lane >> 3, lr = lane & 7;
    const int NK = K / BKH;

    float acc[4][4][4];
#pragma unroll
    for (int i = 0; i < 4; i++)
#pragma unroll
        for (int j = 0; j < 4; j++)
#pragma unroll
            for (int q = 0; q < 4; q++) acc[i][j][q] = 0.f;

#pragma unroll
    for (int s = 0; s < STAGES - 1; s++) {
        load_stage(sb + s * STAGE_BYTES, m0, n0, s * BKH, K, tid);
        asm volatile("cp.async.commit_group;");
    }

    for (int ch = 0; ch < NK; ch++) {
        asm volatile("cp.async.wait_group %0;" :: "n"(STAGES - 2));
        __syncthreads();

        int pf = ch + STAGES - 1;
        if (pf < NK)
            load_stage(sb + (pf % STAGES) * STAGE_BYTES, m0, n0, pf * BKH, K, tid);
        asm volatile("cp.async.commit_group;");

        uint32_t sa = sb + (ch % STAGES) * STAGE_BYTES;
        uint32_t aH = sa, aL = sa + 16384, bH = sa + 32768, bL = sa + 49152;

#pragma unroll
        for (int ks = 0; ks < 4; ks++) {
            int kb = ks * 32;
            uint32_t Bh[4][2], Bl[4][2];
#pragma unroll
            for (int np = 0; np < 2; np++) {
                int nrow = wn + np * 16 + (grp >> 1) * 8 + lr;
                int kbyte = kb + (grp & 1) * 16;
                uint32_t r0, r1, r2, r3;
                LDSM4(r0, r1, r2, r3, swz(bH, nrow, kbyte));
                Bh[np * 2][0] = r0; Bh[np * 2][1] = r1;
                Bh[np * 2 + 1][0] = r2; Bh[np * 2 + 1][1] = r3;
                LDSM4(r0, r1, r2, r3, swz(bL, nrow, kbyte));
                Bl[np * 2][0] = r0; Bl[np * 2][1] = r1;
                Bl[np * 2 + 1][0] = r2; Bl[np * 2 + 1][1] = r3;
            }
#pragma unroll
            for (int mi = 0; mi < 4; mi++) {
                int arow = wm + mi * 16 + (grp & 1) * 8 + lr;
                int kbyte = kb + (grp >> 1) * 16;
                uint32_t a0, a1, a2, a3, l0, l1, l2, l3;
                LDSM4(a0, a1, a2, a3, swz(aH, arow, kbyte));
                LDSM4(l0, l1, l2, l3, swz(aL, arow, kbyte));
#pragma unroll
                for (int ni = 0; ni < 4; ni++) {
                    MMA16816(acc[mi][ni], a0, a1, a2, a3, Bh[ni][0], Bh[ni][1]);
                    MMA16816(acc[mi][ni], a0, a1, a2, a3, Bl[ni][0], Bl[ni][1]);
                    MMA16816(acc[mi][ni], l0, l1, l2, l3, Bh[ni][0], Bh[ni][1]);
                }
            }
        }
        __syncthreads();
    }

    const float sc = 9.313225746154785e-10f;  // 2^-30
    int gid = lane >> 2, tig = lane & 3;
#pragma unroll
    for (int mi = 0; mi < 4; mi++) {
#pragma unroll
        for (int ni = 0; ni < 4; ni++) {
            int r = m0 + wm + mi * 16 + gid;
            int c = n0 + wn + ni * 8 + tig * 2;
            float2 v0 = make_float2(acc[mi][ni][0] * sc, acc[mi][ni][1] * sc);
            float2 v1 = make_float2(acc[mi][ni][2] * sc, acc[mi][ni][3] * sc);
            *(float2*)&g_h[(size_t)r * N + c] = v0;
            *(float2*)&g_h[(size_t)(r + 8) * N + c] = v1;
        }
    }
}

// ---------------------------------------------------------------------------
// Column stats: 32-way batch split (deterministic fp64 partials)
// ---------------------------------------------------------------------------
__global__ void stats_part_kernel(int Bsz, int C) {
    int c = blockIdx.x * 256 + threadIdx.x;
    if (c >= C) return;
    int rows = Bsz / NSPLIT;
    int r0 = blockIdx.y * rows;
    double s = 0, q = 0;
    for (int r = 0; r < rows; r++) {
        float v = g_h[(size_t)(r0 + r) * C + c];
        s += v; q += (double)v * v;
    }
    g_psum[(size_t)blockIdx.y * C + c] = s;
    g_psumsq[(size_t)blockIdx.y * C + c] = q;
}
__global__ void stats_final_kernel(const float* __restrict__ gamma,
                                   const float* __restrict__ beta, int Bsz, int C) {
    int c = blockIdx.x * blockDim.x + threadIdx.x;
    if (c >= C) return;
    double s = 0, q = 0;
    for (int i = 0; i < NSPLIT; i++) {
        s += g_psum[(size_t)i * C + c];
        q += g_psumsq[(size_t)i * C + c];
    }
    double mean = s / (double)Bsz;
    double var = q / (double)Bsz - mean * mean;
    double inv = 1.0 / sqrt(var + 1e-5);
    float sc = (float)((double)gamma[c] * inv);
    g_scale[c] = sc;
    g_bias[c] = beta[c] - (float)mean * sc;
}

// ---------------------------------------------------------------------------
// Per-row: BN+ReLU(approx) -> radix top-(k+32) candidates -> exact serial-FFMA
// refinement -> exact rank/top-k -> sparse decode. One block (256 thr) per row.
// ---------------------------------------------------------------------------
__global__ __launch_bounds__(256) void topk_refine_decode_kernel(
    const float* __restrict__ x, const float* __restrict__ W_enc,
    const float* __restrict__ b_dec, const int* __restrict__ topk_p,
    float* __restrict__ out, int C, int D) {
    extern __shared__ float sm[];
    float* vals = sm;                          // C floats (radix phase)
    unsigned* hist = (unsigned*)(vals + C);    // 2048
    unsigned* chunks = hist + 2048;            // 256
    float* xrow = sm;                          // reuse after selection (D floats)

    __shared__ int s_selIdx[NCAND];
    __shared__ float s_exVal[NCAND];
    __shared__ int s_fIdx[128];
    __shared__ float s_fVal[128];
    __shared__ int s_eqIdx[256];
    __shared__ int s_nsel, s_neq, s_need, s_chunk, s_flagzero;
    __shared__ unsigned s_prefix;

    int row = blockIdx.x;
    int tid = threadIdx.x;
    int k = *topk_p;
    if (k > C) k = C;
    if (k > 128) k = 128;                      // problem uses 64
    int kc = k + 32;                           // candidate margin
    if (kc > C) kc = C;
    if (kc > NCAND) kc = NCAND;

    // BN + ReLU (approx) into smem (force +0.0 so key==0 <=> value==0)
    for (int c = tid; c < C; c += 256) {
        float v = g_h[(size_t)row * C + c];
        v = v * g_scale[c] + g_bias[c];
        vals[c] = (v > 0.f) ? v : 0.f;
    }
    if (tid == 0) { s_nsel = 0; s_neq = 0; s_need = kc; s_prefix = 0u; s_flagzero = 0; }
    __syncthreads();

    // ---- exact radix threshold for kc-th approx value ----
    {
        const int shifts[3] = {21, 10, 0};
        const int nbitsA[3] = {11, 11, 10};
        const unsigned maskHi[3] = {0u, 0xFFE00000u, 0xFFFFFC00u};

        for (int r = 0; r < 3; r++) {
            int nb = 1 << nbitsA[r];
            for (int i = tid; i < nb; i += 256) hist[i] = 0u;
            __syncthreads();

            unsigned pre = s_prefix, mh = maskHi[r], msk = (unsigned)(nb - 1);
            int sh = shifts[r];
            for (int c = tid; c < C; c += 256) {
                unsigned key = __float_as_uint(vals[c]);
                if (key != 0u && (key & mh) == pre)
                    atomicAdd(&hist[(key >> sh) & msk], 1u);
            }
            __syncthreads();

            int NCH = nb >> 3;
            unsigned csum = 0u;
            if (tid < NCH) {
#pragma unroll
                for (int j = 0; j < 8; j++) csum += hist[tid * 8 + j];
                chunks[tid] = csum;
            }
            __syncthreads();
            for (int off = 1; off < NCH; off <<= 1) {
                unsigned add = 0u;
                if (tid < NCH && tid + off < NCH) add = chunks[tid + off];
                __syncthreads();
                if (tid < NCH) chunks[tid] += add;
                __syncthreads();
            }

            int need = s_need;
            if (tid < NCH) {
                int incl = (int)chunks[tid];
                int excl = incl - (int)csum;
                if (excl < need && incl >= need) s_chunk = tid;
                if (tid == 0 && incl < need) s_flagzero = 1;
            }
            __syncthreads();
            if (s_flagzero) break;

            if (tid == 0) {
                int t = s_chunk;
                unsigned cs = 0u;
#pragma unroll
                for (int j = 0; j < 8; j++) cs += hist[t * 8 + j];
                int cum = (int)chunks[t] - (int)cs;
                for (int j = 7; j >= 0; j--) {
                    int hc = (int)hist[t * 8 + j];
                    cum += hc;
                    if (cum >= need) {
                        s_prefix |= ((unsigned)(t * 8 + j)) << sh;
                        s_need = need - (cum - hc);
                        break;
                    }
                }
            }
            __syncthreads();
        }
        __syncthreads();

        unsigned T = s_prefix;
        int need_eq = s_need;
        bool zeroThresh = (s_flagzero != 0);

        // candidate collection
        for (int c = tid; c < C; c += 256) {
            unsigned key = __float_as_uint(vals[c]);
            if (key == 0u) continue;
            if (zeroThresh || key > T) {
                int p = atomicAdd(&s_nsel, 1);
                if (p < NCAND) s_selIdx[p] = c;
            } else if (key == T) {
                int p = atomicAdd(&s_neq, 1);
                if (p < 256) s_eqIdx[p] = c;
            }
        }
        __syncthreads();

        if (!zeroThresh && tid == 0) {
            int ne = s_neq; if (ne > 256) ne = 256;
            for (int i = 1; i < ne; i++) {
                int v = s_eqIdx[i]; int j = i - 1;
                while (j >= 0 && s_eqIdx[j] > v) { s_eqIdx[j + 1] = s_eqIdx[j]; j--; }
                s_eqIdx[j + 1] = v;
            }
            int take = need_eq; if (take > ne) take = ne;
            int base = s_nsel;
            for (int i = 0; i < take; i++) {
                int p = base + i;
                if (p < NCAND) s_selIdx[p] = s_eqIdx[i];
            }
            s_nsel = base + take;
        }
        __syncthreads();
    }

    int ncand = s_nsel; if (ncand > NCAND) ncand = NCAND;
    int myc = (tid < ncand) ? s_selIdx[tid] : -1;
    __syncthreads();

    // ---- load x row into smem (overwrites vals[0..D)) ----
    for (int d = tid; d < D; d += 256) xrow[d] = x[(size_t)row * D + d];
    __syncthreads();

    // ---- exact serial ascending-k FFMA dot per candidate ----
    float facc = 0.f;
    if (myc >= 0) {
        const float4* wr = (const float4*)(W_enc + (size_t)myc * D);
        const int NIT = D >> 2;
        float4 buf[16];
#pragma unroll
        for (int p = 0; p < 16; p++) buf[p] = wr[p];
        for (int i = 0; i < NIT; i++) {
            float4 w = buf[i & 15];
            int pi = i + 16;
            if (pi < NIT) buf[i & 15] = wr[pi];
            const float* xq = &xrow[i << 2];
            facc = __fmaf_rn(xq[0], w.x, facc);
            facc = __fmaf_rn(xq[1], w.y, facc);
            facc = __fmaf_rn(xq[2], w.z, facc);
            facc = __fmaf_rn(xq[3], w.w, facc);
        }
        float bn = __fmaf_rn(facc, g_scale[myc], g_bias[myc]);
        s_exVal[tid] = (bn > 0.f) ? bn : 0.f;
    }
    __syncthreads();

    // ---- exact rank (value desc, index asc) and top-k selection ----
    int kk = (k < ncand) ? k : ncand;
    if (tid < ncand) {
        float vj = s_exVal[tid]; int cj = myc;
        int rank = 0;
        for (int i = 0; i < ncand; i++) {
            float vi = s_exVal[i]; int ci = s_selIdx[i];
            if (vi > vj || (vi == vj && ci < cj)) rank++;
        }
        if (rank < kk) { s_fVal[rank] = vj; s_fIdx[rank] = cj; }
    }
    __syncthreads();

    // ---- sparse decode: recon = sum v_j * WnT[c_j,:] + b_dec ----
    for (int dbase = 0; dbase < D; dbase += 1024) {
        int d = dbase + tid * 4;
        if (d + 3 < D) {
            float4 acc = *(const float4*)(b_dec + d);
            for (int j = 0; j < kk; j++) {
                int ci = s_fIdx[j];
                float v = s_fVal[j];
                float4 w = *(const float4*)(&g_WnT[(size_t)ci * D + d]);
                acc.x += v * w.x; acc.y += v * w.y;
                acc.z += v * w.z; acc.w += v * w.w;
            }
            *(float4*)(out + (size_t)row * D + d) = acc;
        }
    }
}

// ---------------------------------------------------------------------------
// Launch
// ---------------------------------------------------------------------------
extern "C" void kernel_launch(void* const* d_in, const int* in_sizes, int n_in,
                              void* d_out, int out_size) {
    const float* x = (const float*)d_in[0];
    const float* W_enc = (const float*)d_in[1];
    const float* gamma = (const float*)d_in[3];
    const float* beta = (const float*)d_in[4];
    const float* W_dec = (const float*)d_in[5];
    const float* b_dec = (const float*)d_in[6];
    const int* topk = (const int*)d_in[7];

    int D = in_sizes[6];          // K
    int C = in_sizes[2];          // N
    int B = in_sizes[0] / D;      // M
    float* out = (float*)d_out;

    int nx = B * D, nw = C * D;
    split_x_kernel<<<(nx + 255) / 256, 256>>>(x, nx);
    split_w_kernel<<<(nw + 255) / 256, 256>>>(W_enc, nw);

    colnorm_kernel<<<(C + 255) / 256, 256>>>(W_dec, D, C);

    dim3 tg((C + 31) / 32, (D + 31) / 32);
    transpose_kernel<<<tg, dim3(32, 8)>>>(W_dec, D, C);

    cudaFuncSetAttribute(hgemm_kernel,
                         cudaFuncAttributeMaxDynamicSharedMemorySize, GEMM_SMEM);
    dim3 gg(B / 128, C / 128);   // m fast -> concurrent CTAs share B tiles in L2
    hgemm_kernel<<<gg, 256, GEMM_SMEM>>>(B, C, D);

    dim3 sg((C + 255) / 256, NSPLIT);
    stats_part_kernel<<<sg, 256>>>(B, C);
    stats_final_kernel<<<(C + 255) / 256, 256>>>(gamma, beta, B, C);

    size_t dyn = (size_t)C * sizeof(float) + 2048 * sizeof(unsigned) + 256 * sizeof(unsigned);
    cudaFuncSetAttribute(topk_refine_decode_kernel,
                         cudaFuncAttributeMaxDynamicSharedMemorySize, (int)dyn);
    topk_refine_decode_kernel<<<B, 256, dyn>>>(x, W_enc, b_dec, topk, out, C, D);
}

// round 6
// speedup vs baseline: 1.2953x; 1.0608x over previous
#include <cuda_runtime.h>
#include <cuda_fp16.h>
#include <cstdint>

// B=4096, D(K)=2048, C=16384, topk=64
// recon = TopK(BN(x @ W_enc^T)) @ normalize_cols(W_dec)^T + b_dec
// b_enc cancels inside batch-norm -> skipped everywhere (consistent).
//
// R4-proven numerics: split-fp16 HMMA GEMM (hh+hl+lh, sigma~2e-6) -> fp32 h.
// h feeds BN batch stats (needs h sigma <= 7e-6: split REQUIRED, R5 lesson)
// and top-(k+32) candidate generation. Candidates recomputed with the exact
// serial ascending-k FFMA fp32 chain, exact-ranked, top-k'ed, decoded.
// R6 change: GEMM BK 64->32 (96KB smem -> 2 CTAs/SM) for latency hiding.

#define MAX_B 4096
#define MAX_C 16384
#define MAX_D 2048
#define NSPLIT 32
#define NCAND 160

__device__ float g_h[(size_t)MAX_B * MAX_C];        // 256 MB approx pre-BN activations
__device__ float g_WnT[(size_t)MAX_C * MAX_D];      // 128 MB normalized decoder [C,D]
__device__ float g_inv_norm[MAX_C];
__device__ float g_scale[MAX_C];
__device__ float g_bias[MAX_C];
__device__ double g_psum[NSPLIT * MAX_C];
__device__ double g_psumsq[NSPLIT * MAX_C];
__device__ __half g_xh[(size_t)MAX_B * MAX_D];
__device__ __half g_xl[(size_t)MAX_B * MAX_D];
__device__ __half g_wh[(size_t)MAX_C * MAX_D];
__device__ __half g_wl[(size_t)MAX_C * MAX_D];

// ---------------------------------------------------------------------------
// fp16 split kernels (power-of-2 pre-scaling keeps residuals normal-range)
// ---------------------------------------------------------------------------
__global__ void split_x_kernel(const float* __restrict__ src, int n) {
    int i = blockIdx.x * blockDim.x + threadIdx.x;
    if (i >= n) return;
    float s = src[i] * 4096.0f;                  // 2^12, exact
    __half h = __float2half_rn(s);
    g_xh[i] = h;
    g_xl[i] = __float2half_rn(s - __half2float(h));
}
__global__ void split_w_kernel(const float* __restrict__ src, int n) {
    int i = blockIdx.x * blockDim.x + threadIdx.x;
    if (i >= n) return;
    float s = src[i] * 262144.0f;                // 2^18, exact
    __half h = __float2half_rn(s);
    g_wh[i] = h;
    g_wl[i] = __float2half_rn(s - __half2float(h));
}

// ---------------------------------------------------------------------------
// W_dec column inv-norms (fp64)
// ---------------------------------------------------------------------------
__global__ void colnorm_kernel(const float* __restrict__ Wdec, int D, int C) {
    int c = blockIdx.x * blockDim.x + threadIdx.x;
    if (c >= C) return;
    double s0 = 0, s1 = 0, s2 = 0, s3 = 0;
    int d = 0;
    for (; d + 3 < D; d += 4) {
        float w0 = Wdec[(size_t)(d + 0) * C + c];
        float w1 = Wdec[(size_t)(d + 1) * C + c];
        float w2 = Wdec[(size_t)(d + 2) * C + c];
        float w3 = Wdec[(size_t)(d + 3) * C + c];
        s0 += (double)w0 * w0; s1 += (double)w1 * w1;
        s2 += (double)w2 * w2; s3 += (double)w3 * w3;
    }
    for (; d < D; d++) { float w = Wdec[(size_t)d * C + c]; s0 += (double)w * w; }
    double n = sqrt(s0 + s1 + s2 + s3);
    if (n < 1e-12) n = 1e-12;
    g_inv_norm[c] = (float)(1.0 / n);
}

// ---------------------------------------------------------------------------
// Transpose + scale: WnT[c,d] = W_dec[d,c] * inv_norm[c]
// ---------------------------------------------------------------------------
__global__ void transpose_kernel(const float* __restrict__ Wdec, int D, int C) {
    __shared__ float tile[32][33];
    int c0 = blockIdx.x * 32, d0 = blockIdx.y * 32;
    for (int i = threadIdx.y; i < 32; i += 8) {
        int d = d0 + i, c = c0 + threadIdx.x;
        tile[i][threadIdx.x] = (d < D && c < C) ? Wdec[(size_t)d * C + c] : 0.f;
    }
    __syncthreads();
    for (int i = threadIdx.y; i < 32; i += 8) {
        int c = c0 + i, d = d0 + threadIdx.x;
        if (c < C && d < D)
            g_WnT[(size_t)c * D + d] = tile[threadIdx.x][i] * g_inv_norm[c];
    }
}

// ---------------------------------------------------------------------------
// mma.sync split-fp16 GEMM (approx h): 128x128 tile, BK=32, 3-stage cp.async,
// SW64 swizzle (64B rows), 32KB/stage -> 96KB -> 2 CTAs/SM.
// ---------------------------------------------------------------------------
#define BKH 32
#define MAT_BYTES 8192           // 128 rows x 32 halves x 2B
#define STAGE_BYTES 32768        // 4 matrices
#define STAGES 3
#define GEMM_SMEM (STAGES * STAGE_BYTES)

#define LDSM4(R0, R1, R2, R3, ADDR) \
    asm volatile("ldmatrix.sync.aligned.m8n8.x4.shared.b16 {%0,%1,%2,%3}, [%4];" \
                 : "=r"(R0), "=r"(R1), "=r"(R2), "=r"(R3) : "r"(ADDR))

#define MMA16816(CC, A0, A1, A2, A3, B0, B1) \
    asm volatile("mma.sync.aligned.m16n8k16.row.col.f32.f16.f16.f32 " \
                 "{%0,%1,%2,%3}, {%4,%5,%6,%7}, {%8,%9}, {%0,%1,%2,%3};" \
                 : "+f"((CC)[0]), "+f"((CC)[1]), "+f"((CC)[2]), "+f"((CC)[3]) \
                 : "r"(A0), "r"(A1), "r"(A2), "r"(A3), "r"(B0), "r"(B1))

__device__ __forceinline__ uint32_t smem_u32(const void* p) {
    uint32_t a;
    asm("{ .reg .u64 t; cvta.to.shared.u64 t, %1; cvt.u32.u64 %0, t; }" : "=r"(a) : "l"(p));
    return a;
}
// SW64 swizzle: 64B rows, off ^ ((off>>3)&0x30). Same function for write & read.
__device__ __forceinline__ uint32_t swz64(uint32_t base, int row, int kbyte) {
    uint32_t off = row * 64 + kbyte;
    return base + (off ^ ((off >> 3) & 0x30));
}
__device__ __forceinline__ void cpasync16(uint32_t sa, const void* g) {
    asm volatile("cp.async.cg.shared.global [%0], [%1], 16;" :: "r"(sa), "l"(g));
}

__device__ __forceinline__ void load_stage(uint32_t sbase, int m0, int n0,
                                           int k0, int K, int tid) {
    const __half* srcs[4] = {g_xh, g_xl, g_wh, g_wl};
    int r0s[4] = {m0, m0, n0, n0};
#pragma unroll
    for (int mat = 0; mat < 4; mat++) {
        const __half* src = srcs[mat];
        int r0 = r0s[mat];
#pragma unroll
        for (int s = 0; s < 2; s++) {
            int idx = tid * 2 + s;             // 0..511
            int row = idx >> 2, seg = idx & 3; // 128 rows x 4 16B-segments
            const __half* g = src + (size_t)(r0 + row) * K + k0 + seg * 8;
            cpasync16(swz64(sbase + mat * MAT_BYTES, row, seg * 16), g);
        }
    }
}

__global__ __launch_bounds__(256, 2)
void hgemm_kernel(int M, int N, int K) {
    extern __shared__ __align__(1024) char smem[];
    const uint32_t sb = smem_u32(smem);
    const int tid = threadIdx.x;
    const int wid = tid >> 5, lane = tid & 31;
    const int wm = (wid & 1) * 64;      // warp tile 64 (M) x 32 (N)
    const int wn = (wid >> 1) * 32;
    const int m0 = blockIdx.x * 128;
    const int n0 = blockIdx.y * 128;
    const int grp = lane >> 3, lr = lane & 7;
    const int NK = K / BKH;

    float acc[4][4][4];
#pragma unroll
    for (int i = 0; i < 4; i++)
#pragma unroll
        for (int j = 0; j < 4; j++)
#pragma unroll
            for (int q = 0; q < 4; q++) acc[i][j][q] = 0.f;

#pragma unroll
    for (int s = 0; s < STAGES - 1; s++) {
        load_stage(sb + s * STAGE_BYTES, m0, n0, s * BKH, K, tid);
        asm volatile("cp.async.commit_group;");
    }

    for (int ch = 0; ch < NK; ch++) {
        asm volatile("cp.async.wait_group %0;" :: "n"(STAGES - 2));
        __syncthreads();

        int pf = ch + STAGES - 1;
        if (pf < NK)
            load_stage(sb + (pf % STAGES) * STAGE_BYTES, m0, n0, pf * BKH, K, tid);
        asm volatile("cp.async.commit_group;");

        uint32_t sa = sb + (ch % STAGES) * STAGE_BYTES;
        uint32_t aH = sa, aL = sa + MAT_BYTES;
        uint32_t bH = sa + 2 * MAT_BYTES, bL = sa + 3 * MAT_BYTES;

#pragma unroll
        for (int ks = 0; ks < 2; ks++) {
            int kb = ks * 32;                  // byte offset of 16-half kstep
            uint32_t Bh[4][2], Bl[4][2];
#pragma unroll
            for (int np = 0; np < 2; np++) {
                int nrow = wn + np * 16 + (grp >> 1) * 8 + lr;
                int kbyte = kb + (grp & 1) * 16;
                uint32_t r0, r1, r2, r3;
                LDSM4(r0, r1, r2, r3, swz64(bH, nrow, kbyte));
                Bh[np * 2][0] = r0; Bh[np * 2][1] = r1;
                Bh[np * 2 + 1][0] = r2; Bh[np * 2 + 1][1] = r3;
                LDSM4(r0, r1, r2, r3, swz64(bL, nrow, kbyte));
                Bl[np * 2][0] = r0; Bl[np * 2][1] = r1;
                Bl[np * 2 + 1][0] = r2; Bl[np * 2 + 1][1] = r3;
            }
#pragma unroll
            for (int mi = 0; mi < 4; mi++) {
                int arow = wm + mi * 16 + (grp & 1) * 8 + lr;
                int kbyte = kb + (grp >> 1) * 16;
                uint32_t a0, a1, a2, a3, l0, l1, l2, l3;
                LDSM4(a0, a1, a2, a3, swz64(aH, arow, kbyte));
                LDSM4(l0, l1, l2, l3, swz64(aL, arow, kbyte));
#pragma unroll
                for (int ni = 0; ni < 4; ni++) {
                    MMA16816(acc[mi][ni], a0, a1, a2, a3, Bh[ni][0], Bh[ni][1]);
                    MMA16816(acc[mi][ni], a0, a1, a2, a3, Bl[ni][0], Bl[ni][1]);
                    MMA16816(acc[mi][ni], l0, l1, l2, l3, Bh[ni][0], Bh[ni][1]);
                }
            }
        }
        __syncthreads();
    }

    // epilogue: scale by 2^-30 (undo 2^12 * 2^18) and store
    const float sc = 9.313225746154785e-10f;  // 2^-30
    int gid = lane >> 2, tig = lane & 3;
#pragma unroll
    for (int mi = 0; mi < 4; mi++) {
#pragma unroll
        for (int ni = 0; ni < 4; ni++) {
            int r = m0 + wm + mi * 16 + gid;
            int c = n0 + wn + ni * 8 + tig * 2;
            float2 v0 = make_float2(acc[mi][ni][0] * sc, acc[mi][ni][1] * sc);
            float2 v1 = make_float2(acc[mi][ni][2] * sc, acc[mi][ni][3] * sc);
            *(float2*)&g_h[(size_t)r * N + c] = v0;
            *(float2*)&g_h[(size_t)(r + 8) * N + c] = v1;
        }
    }
}

// ---------------------------------------------------------------------------
// Column stats: 32-way batch split (deterministic fp64 partials)
// ---------------------------------------------------------------------------
__global__ void stats_part_kernel(int Bsz, int C) {
    int c = blockIdx.x * 256 + threadIdx.x;
    if (c >= C) return;
    int rows = Bsz / NSPLIT;
    int r0 = blockIdx.y * rows;
    double s = 0, q = 0;
    for (int r = 0; r < rows; r++) {
        float v = g_h[(size_t)(r0 + r) * C + c];
        s += v; q += (double)v * v;
    }
    g_psum[(size_t)blockIdx.y * C + c] = s;
    g_psumsq[(size_t)blockIdx.y * C + c] = q;
}
__global__ void stats_final_kernel(const float* __restrict__ gamma,
                                   const float* __restrict__ beta, int Bsz, int C) {
    int c = blockIdx.x * blockDim.x + threadIdx.x;
    if (c >= C) return;
    double s = 0, q = 0;
    for (int i = 0; i < NSPLIT; i++) {
        s += g_psum[(size_t)i * C + c];
        q += g_psumsq[(size_t)i * C + c];
    }
    double mean = s / (double)Bsz;
    double var = q / (double)Bsz - mean * mean;
    double inv = 1.0 / sqrt(var + 1e-5);
    float sc = (float)((double)gamma[c] * inv);
    g_scale[c] = sc;
    g_bias[c] = beta[c] - (float)mean * sc;
}

// ---------------------------------------------------------------------------
// Per-row: BN+ReLU(approx) -> radix top-(k+32) candidates -> exact serial-FFMA
// refinement -> exact rank/top-k -> sparse decode. One block (256 thr) per row.
// ---------------------------------------------------------------------------
__global__ __launch_bounds__(256) void topk_refine_decode_kernel(
    const float* __restrict__ x, const float* __restrict__ W_enc,
    const float* __restrict__ b_dec, const int* __restrict__ topk_p,
    float* __restrict__ out, int C, int D) {
    extern __shared__ float sm[];
    float* vals = sm;                          // C floats (radix phase)
    unsigned* hist = (unsigned*)(vals + C);    // 2048
    unsigned* chunks = hist + 2048;            // 256
    float* xrow = sm;                          // reuse after selection (D floats)

    __shared__ int s_selIdx[NCAND];
    __shared__ float s_exVal[NCAND];
    __shared__ int s_fIdx[128];
    __shared__ float s_fVal[128];
    __shared__ int s_eqIdx[256];
    __shared__ int s_nsel, s_neq, s_need, s_chunk, s_flagzero;
    __shared__ unsigned s_prefix;

    int row = blockIdx.x;
    int tid = threadIdx.x;
    int k = *topk_p;
    if (k > C) k = C;
    if (k > 128) k = 128;                      // problem uses 64
    int kc = k + 32;                           // candidate margin
    if (kc > C) kc = C;
    if (kc > NCAND) kc = NCAND;

    // BN + ReLU (approx) into smem (force +0.0 so key==0 <=> value==0)
    for (int c = tid; c < C; c += 256) {
        float v = g_h[(size_t)row * C + c];
        v = v * g_scale[c] + g_bias[c];
        vals[c] = (v > 0.f) ? v : 0.f;
    }
    if (tid == 0) { s_nsel = 0; s_neq = 0; s_need = kc; s_prefix = 0u; s_flagzero = 0; }
    __syncthreads();

    // ---- exact radix threshold for kc-th approx value ----
    {
        const int shifts[3] = {21, 10, 0};
        const int nbitsA[3] = {11, 11, 10};
        const unsigned maskHi[3] = {0u, 0xFFE00000u, 0xFFFFFC00u};

        for (int r = 0; r < 3; r++) {
            int nb = 1 << nbitsA[r];
            for (int i = tid; i < nb; i += 256) hist[i] = 0u;
            __syncthreads();

            unsigned pre = s_prefix, mh = maskHi[r], msk = (unsigned)(nb - 1);
            int sh = shifts[r];
            for (int c = tid; c < C; c += 256) {
                unsigned key = __float_as_uint(vals[c]);
                if (key != 0u && (key & mh) == pre)
                    atomicAdd(&hist[(key >> sh) & msk], 1u);
            }
            __syncthreads();

            int NCH = nb >> 3;
            unsigned csum = 0u;
            if (tid < NCH) {
#pragma unroll
                for (int j = 0; j < 8; j++) csum += hist[tid * 8 + j];
                chunks[tid] = csum;
            }
            __syncthreads();
            for (int off = 1; off < NCH; off <<= 1) {
                unsigned add = 0u;
                if (tid < NCH && tid + off < NCH) add = chunks[tid + off];
                __syncthreads();
                if (tid < NCH) chunks[tid] += add;
                __syncthreads();
            }

            int need = s_need;
            if (tid < NCH) {
                int incl = (int)chunks[tid];
                int excl = incl - (int)csum;
                if (excl < need && incl >= need) s_chunk = tid;
                if (tid == 0 && incl < need) s_flagzero = 1;
            }
            __syncthreads();
            if (s_flagzero) break;

            if (tid == 0) {
                int t = s_chunk;
                unsigned cs = 0u;
#pragma unroll
                for (int j = 0; j < 8; j++) cs += hist[t * 8 + j];
                int cum = (int)chunks[t] - (int)cs;
                for (int j = 7; j >= 0; j--) {
                    int hc = (int)hist[t * 8 + j];
                    cum += hc;
                    if (cum >= need) {
                        s_prefix |= ((unsigned)(t * 8 + j)) << sh;
                        s_need = need - (cum - hc);
                        break;
                    }
                }
            }
            __syncthreads();
        }
        __syncthreads();

        unsigned T = s_prefix;
        int need_eq = s_need;
        bool zeroThresh = (s_flagzero != 0);

        // candidate collection
        for (int c = tid; c < C; c += 256) {
            unsigned key = __float_as_uint(vals[c]);
            if (key == 0u) continue;
            if (zeroThresh || key > T) {
                int p = atomicAdd(&s_nsel, 1);
                if (p < NCAND) s_selIdx[p] = c;
            } else if (key == T) {
                int p = atomicAdd(&s_neq, 1);
                if (p < 256) s_eqIdx[p] = c;
            }
        }
        __syncthreads();

        if (!zeroThresh && tid == 0) {
            int ne = s_neq; if (ne > 256) ne = 256;
            for (int i = 1; i < ne; i++) {
                int v = s_eqIdx[i]; int j = i - 1;
                while (j >= 0 && s_eqIdx[j] > v) { s_eqIdx[j + 1] = s_eqIdx[j]; j--; }
                s_eqIdx[j + 1] = v;
            }
            int take = need_eq; if (take > ne) take = ne;
            int base = s_nsel;
            for (int i = 0; i < take; i++) {
                int p = base + i;
                if (p < NCAND) s_selIdx[p] = s_eqIdx[i];
            }
            s_nsel = base + take;
        }
        __syncthreads();
    }

    int ncand = s_nsel; if (ncand > NCAND) ncand = NCAND;
    int myc = (tid < ncand) ? s_selIdx[tid] : -1;
    __syncthreads();

    // ---- load x row into smem (overwrites vals[0..D)) ----
    for (int d = tid; d < D; d += 256) xrow[d] = x[(size_t)row * D + d];
    __syncthreads();

    // ---- exact serial ascending-k FFMA dot per candidate ----
    float facc = 0.f;
    if (myc >= 0) {
        const float4* wr = (const float4*)(W_enc + (size_t)myc * D);
        const int NIT = D >> 2;
        float4 buf[16];
#pragma unroll
        for (int p = 0; p < 16; p++) buf[p] = wr[p];
        for (int i = 0; i < NIT; i++) {
            float4 w = buf[i & 15];
            int pi = i + 16;
            if (pi < NIT) buf[i & 15] = wr[pi];
            const float* xq = &xrow[i << 2];
            facc = __fmaf_rn(xq[0], w.x, facc);
            facc = __fmaf_rn(xq[1], w.y, facc);
            facc = __fmaf_rn(xq[2], w.z, facc);
            facc = __fmaf_rn(xq[3], w.w, facc);
        }
        float bn = __fmaf_rn(facc, g_scale[myc], g_bias[myc]);
        s_exVal[tid] = (bn > 0.f) ? bn : 0.f;
    }
    __syncthreads();

    // ---- exact rank (value desc, index asc) and top-k selection ----
    int kk = (k < ncand) ? k : ncand;
    if (tid < ncand) {
        float vj = s_exVal[tid]; int cj = myc;
        int rank = 0;
        for (int i = 0; i < ncand; i++) {
            float vi = s_exVal[i]; int ci = s_selIdx[i];
            if (vi > vj || (vi == vj && ci < cj)) rank++;
        }
        if (rank < kk) { s_fVal[rank] = vj; s_fIdx[rank] = cj; }
    }
    __syncthreads();

    // ---- sparse decode: recon = sum v_j * WnT[c_j,:] + b_dec ----
    for (int dbase = 0; dbase < D; dbase += 1024) {
        int d = dbase + tid * 4;
        if (d + 3 < D) {
            float4 acc = *(const float4*)(b_dec + d);
            for (int j = 0; j < kk; j++) {
                int ci = s_fIdx[j];
                float v = s_fVal[j];
                float4 w = *(const float4*)(&g_WnT[(size_t)ci * D + d]);
                acc.x += v * w.x; acc.y += v * w.y;
                acc.z += v * w.z; acc.w += v * w.w;
            }
            *(float4*)(out + (size_t)row * D + d) = acc;
        }
    }
}

// ---------------------------------------------------------------------------
// Launch
// ---------------------------------------------------------------------------
extern "C" void kernel_launch(void* const* d_in, const int* in_sizes, int n_in,
                              void* d_out, int out_size) {
    const float* x = (const float*)d_in[0];
    const float* W_enc = (const float*)d_in[1];
    const float* gamma = (const float*)d_in[3];
    const float* beta = (const float*)d_in[4];
    const float* W_dec = (const float*)d_in[5];
    const float* b_dec = (const float*)d_in[6];
    const int* topk = (const int*)d_in[7];

    int D = in_sizes[6];          // K
    int C = in_sizes[2];          // N
    int B = in_sizes[0] / D;      // M
    float* out = (float*)d_out;

    int nx = B * D, nw = C * D;
    split_x_kernel<<<(nx + 255) / 256, 256>>>(x, nx);
    split_w_kernel<<<(nw + 255) / 256, 256>>>(W_enc, nw);

    colnorm_kernel<<<(C + 255) / 256, 256>>>(W_dec, D, C);

    dim3 tg((C + 31) / 32, (D + 31) / 32);
    transpose_kernel<<<tg, dim3(32, 8)>>>(W_dec, D, C);

    cudaFuncSetAttribute(hgemm_kernel,
                         cudaFuncAttributeMaxDynamicSharedMemorySize, GEMM_SMEM);
    dim3 gg(B / 128, C / 128);   // m fast -> concurrent CTAs share W tiles in L2
    hgemm_kernel<<<gg, 256, GEMM_SMEM>>>(B, C, D);

    dim3 sg((C + 255) / 256, NSPLIT);
    stats_part_kernel<<<sg, 256>>>(B, C);
    stats_final_kernel<<<(C + 255) / 256, 256>>>(gamma, beta, B, C);

    size_t dyn = (size_t)C * sizeof(float) + 2048 * sizeof(unsigned) + 256 * sizeof(unsigned);
    cudaFuncSetAttribute(topk_refine_decode_kernel,
                         cudaFuncAttributeMaxDynamicSharedMemorySize, (int)dyn);
    topk_refine_decode_kernel<<<B, 256, dyn>>>(x, W_enc, b_dec, topk, out, C, D);
}

// round 9
// speedup vs baseline: 1.3473x; 1.0401x over previous
#include <cuda_runtime.h>
#include <cuda_fp16.h>
#include <cstdint>

// B=4096, D(K)=2048, C=16384, topk=64
// recon = TopK(BN(x @ W_enc^T)) @ normalize_cols(W_dec)^T + b_dec
// b_enc cancels inside batch-norm -> skipped everywhere (consistent).
//
// Numerics ledger (R4..R8 lessons):
//  - BN stats: fp64 reduction of split-fp16 fp32 GEMM accumulators (exact-ish).
//  - Candidate generation tolerates ~3e-4 -> h stored fp16, margin 32.
//  - Refinement MUST be the serial ascending-k fp32 FMA chain (R7/R8 showed a
//    different chain structure deterministically swaps a boundary pair).

#define MAX_B 4096
#define MAX_C 16384
#define MAX_D 2048
#define MAX_MT 32            // max M/128 tiles
#define NCAND 160

__device__ __half g_h16[(size_t)MAX_B * MAX_C];     // 128 MB approx pre-BN activations
__device__ float g_WnT[(size_t)MAX_C * MAX_D];      // 128 MB normalized decoder [C,D]
__device__ float g_inv_norm[MAX_C];
__device__ float g_scale[MAX_C];
__device__ float g_bias[MAX_C];
__device__ double g_psum[MAX_MT * MAX_C];           // per-(mtile,col) fp64 partials
__device__ double g_psumsq[MAX_MT * MAX_C];
__device__ __half g_xh[(size_t)MAX_B * MAX_D];
__device__ __half g_xl[(size_t)MAX_B * MAX_D];
__device__ __half g_wh[(size_t)MAX_C * MAX_D];
__device__ __half g_wl[(size_t)MAX_C * MAX_D];

// ---------------------------------------------------------------------------
// fp16 split kernels (power-of-2 pre-scaling keeps residuals normal-range)
// ---------------------------------------------------------------------------
__global__ void split_x_kernel(const float* __restrict__ src, int n) {
    int i = blockIdx.x * blockDim.x + threadIdx.x;
    if (i >= n) return;
    float s = src[i] * 4096.0f;                  // 2^12, exact
    __half h = __float2half_rn(s);
    g_xh[i] = h;
    g_xl[i] = __float2half_rn(s - __half2float(h));
}
__global__ void split_w_kernel(const float* __restrict__ src, int n) {
    int i = blockIdx.x * blockDim.x + threadIdx.x;
    if (i >= n) return;
    float s = src[i] * 262144.0f;                // 2^18, exact
    __half h = __float2half_rn(s);
    g_wh[i] = h;
    g_wl[i] = __float2half_rn(s - __half2float(h));
}

// ---------------------------------------------------------------------------
// W_dec column inv-norms (fp64)
// ---------------------------------------------------------------------------
__global__ void colnorm_kernel(const float* __restrict__ Wdec, int D, int C) {
    int c = blockIdx.x * blockDim.x + threadIdx.x;
    if (c >= C) return;
    double s0 = 0, s1 = 0, s2 = 0, s3 = 0;
    int d = 0;
    for (; d + 3 < D; d += 4) {
        float w0 = Wdec[(size_t)(d + 0) * C + c];
        float w1 = Wdec[(size_t)(d + 1) * C + c];
        float w2 = Wdec[(size_t)(d + 2) * C + c];
        float w3 = Wdec[(size_t)(d + 3) * C + c];
        s0 += (double)w0 * w0; s1 += (double)w1 * w1;
        s2 += (double)w2 * w2; s3 += (double)w3 * w3;
    }
    for (; d < D; d++) { float w = Wdec[(size_t)d * C + c]; s0 += (double)w * w; }
    double n = sqrt(s0 + s1 + s2 + s3);
    if (n < 1e-12) n = 1e-12;
    g_inv_norm[c] = (float)(1.0 / n);
}

// ---------------------------------------------------------------------------
// Transpose + scale: WnT[c,d] = W_dec[d,c] * inv_norm[c]
// ---------------------------------------------------------------------------
__global__ void transpose_kernel(const float* __restrict__ Wdec, int D, int C) {
    __shared__ float tile[32][33];
    int c0 = blockIdx.x * 32, d0 = blockIdx.y * 32;
    for (int i = threadIdx.y; i < 32; i += 8) {
        int d = d0 + i, c = c0 + threadIdx.x;
        tile[i][threadIdx.x] = (d < D && c < C) ? Wdec[(size_t)d * C + c] : 0.f;
    }
    __syncthreads();
    for (int i = threadIdx.y; i < 32; i += 8) {
        int c = c0 + i, d = d0 + threadIdx.x;
        if (c < C && d < D)
            g_WnT[(size_t)c * D + d] = tile[threadIdx.x][i] * g_inv_norm[c];
    }
}

// ---------------------------------------------------------------------------
// mma.sync split-fp16 GEMM: 128x128 tile, BK=32, 3 stages, SW64, 2 CTAs/SM.
// Inner loop: product-outer ordering (acc reuse distance 4).
// Epilogue: h16 store + fused per-CTA column sum/sumsq partials in FP64.
// ---------------------------------------------------------------------------
#define BKH 32
#define MAT_BYTES 8192           // 128 rows x 32 halves x 2B
#define STAGE_BYTES 32768        // 4 matrices
#define STAGES 3
#define GEMM_SMEM (STAGES * STAGE_BYTES)

#define LDSM4(R0, R1, R2, R3, ADDR) \
    asm volatile("ldmatrix.sync.aligned.m8n8.x4.shared.b16 {%0,%1,%2,%3}, [%4];" \
                 : "=r"(R0), "=r"(R1), "=r"(R2), "=r"(R3) : "r"(ADDR))

#define MMA16816(CC, A0, A1, A2, A3, B0, B1) \
    asm volatile("mma.sync.aligned.m16n8k16.row.col.f32.f16.f16.f32 " \
                 "{%0,%1,%2,%3}, {%4,%5,%6,%7}, {%8,%9}, {%0,%1,%2,%3};" \
                 : "+f"((CC)[0]), "+f"((CC)[1]), "+f"((CC)[2]), "+f"((CC)[3]) \
                 : "r"(A0), "r"(A1), "r"(A2), "r"(A3), "r"(B0), "r"(B1))

__device__ __forceinline__ uint32_t smem_u32(const void* p) {
    uint32_t a;
    asm("{ .reg .u64 t; cvta.to.shared.u64 t, %1; cvt.u32.u64 %0, t; }" : "=r"(a) : "l"(p));
    return a;
}
__device__ __forceinline__ uint32_t swz64(uint32_t base, int row, int kbyte) {
    uint32_t off = row * 64 + kbyte;
    return base + (off ^ ((off >> 3) & 0x30));
}
__device__ __forceinline__ void cpasync16(uint32_t sa, const void* g) {
    asm volatile("cp.async.cg.shared.global [%0], [%1], 16;" :: "r"(sa), "l"(g));
}

__device__ __forceinline__ void load_stage(uint32_t sbase, int m0, int n0,
                                           int k0, int K, int tid) {
    const __half* srcs[4] = {g_xh, g_xl, g_wh, g_wl};
    int r0s[4] = {m0, m0, n0, n0};
#pragma unroll
    for (int mat = 0; mat < 4; mat++) {
        const __half* src = srcs[mat];
        int r0 = r0s[mat];
#pragma unroll
        for (int s = 0; s < 2; s++) {
            int idx = tid * 2 + s;             // 0..511
            int row = idx >> 2, seg = idx & 3; // 128 rows x 4 16B-segments
            const __half* g = src + (size_t)(r0 + row) * K + k0 + seg * 8;
            cpasync16(swz64(sbase + mat * MAT_BYTES, row, seg * 16), g);
        }
    }
}

__global__ __launch_bounds__(256, 2)
void hgemm_kernel(int M, int N, int K) {
    extern __shared__ __align__(1024) char smem[];
    const uint32_t sb = smem_u32(smem);
    const int tid = threadIdx.x;
    const int wid = tid >> 5, lane = tid & 31;
    const int wm = (wid & 1) * 64;      // warp tile 64 (M) x 32 (N)
    const int wn = (wid >> 1) * 32;
    const int m0 = blockIdx.x * 128;
    const int n0 = blockIdx.y * 128;
    const int grp = lane >> 3, lr = lane & 7;
    const int NK = K / BKH;

    float acc[4][4][4];
#pragma unroll
    for (int i = 0; i < 4; i++)
#pragma unroll
        for (int j = 0; j < 4; j++)
#pragma unroll
            for (int q = 0; q < 4; q++) acc[i][j][q] = 0.f;

#pragma unroll
    for (int s = 0; s < STAGES - 1; s++) {
        load_stage(sb + s * STAGE_BYTES, m0, n0, s * BKH, K, tid);
        asm volatile("cp.async.commit_group;");
    }

    for (int ch = 0; ch < NK; ch++) {
        asm volatile("cp.async.wait_group %0;" :: "n"(STAGES - 2));
        __syncthreads();

        int pf = ch + STAGES - 1;
        if (pf < NK)
            load_stage(sb + (pf % STAGES) * STAGE_BYTES, m0, n0, pf * BKH, K, tid);
        asm volatile("cp.async.commit_group;");

        uint32_t sa = sb + (ch % STAGES) * STAGE_BYTES;
        uint32_t aH = sa, aL = sa + MAT_BYTES;
        uint32_t bH = sa + 2 * MAT_BYTES, bL = sa + 3 * MAT_BYTES;

#pragma unroll
        for (int ks = 0; ks < 2; ks++) {
            int kb = ks * 32;
            uint32_t Bh[4][2], Bl[4][2];
#pragma unroll
            for (int np = 0; np < 2; np++) {
                int nrow = wn + np * 16 + (grp >> 1) * 8 + lr;
                int kbyte = kb + (grp & 1) * 16;
                uint32_t r0, r1, r2, r3;
                LDSM4(r0, r1, r2, r3, swz64(bH, nrow, kbyte));
                Bh[np * 2][0] = r0; Bh[np * 2][1] = r1;
                Bh[np * 2 + 1][0] = r2; Bh[np * 2 + 1][1] = r3;
                LDSM4(r0, r1, r2, r3, swz64(bL, nrow, kbyte));
                Bl[np * 2][0] = r0; Bl[np * 2][1] = r1;
                Bl[np * 2 + 1][0] = r2; Bl[np * 2 + 1][1] = r3;
            }
#pragma unroll
            for (int mi = 0; mi < 4; mi++) {
                int arow = wm + mi * 16 + (grp & 1) * 8 + lr;
                int kbyte = kb + (grp >> 1) * 16;
                uint32_t a0, a1, a2, a3, l0, l1, l2, l3;
                LDSM4(a0, a1, a2, a3, swz64(aH, arow, kbyte));
                LDSM4(l0, l1, l2, l3, swz64(aL, arow, kbyte));
                // product-outer: same-acc reuse distance = 4 mmas
#pragma unroll
                for (int ni = 0; ni < 4; ni++)
                    MMA16816(acc[mi][ni], a0, a1, a2, a3, Bh[ni][0], Bh[ni][1]);
#pragma unroll
                for (int ni = 0; ni < 4; ni++)
                    MMA16816(acc[mi][ni], a0, a1, a2, a3, Bl[ni][0], Bl[ni][1]);
#pragma unroll
                for (int ni = 0; ni < 4; ni++)
                    MMA16816(acc[mi][ni], l0, l1, l2, l3, Bh[ni][0], Bh[ni][1]);
            }
        }
        __syncthreads();
    }

    // ---- epilogue: h16 store + fused column stats partials (FP64) ----
    const float sc = 9.313225746154785e-10f;  // 2^-30
    int gid = lane >> 2, tig = lane & 3;
#pragma unroll
    for (int mi = 0; mi < 4; mi++) {
#pragma unroll
        for (int ni = 0; ni < 4; ni++) {
            int r = m0 + wm + mi * 16 + gid;
            int c = n0 + wn + ni * 8 + tig * 2;
            *(__half2*)&g_h16[(size_t)r * N + c] =
                __floats2half2_rn(acc[mi][ni][0] * sc, acc[mi][ni][1] * sc);
            *(__half2*)&g_h16[(size_t)(r + 8) * N + c] =
                __floats2half2_rn(acc[mi][ni][2] * sc, acc[mi][ni][3] * sc);
        }
    }

    // per-thread column partials over its 8 rows (4 mi x 2), 8 columns — FP64
    double csum[4][2], csq[4][2];
#pragma unroll
    for (int ni = 0; ni < 4; ni++)
#pragma unroll
        for (int qc = 0; qc < 2; qc++) {
            double s = 0.0, q = 0.0;
#pragma unroll
            for (int mi = 0; mi < 4; mi++) {
                double v1 = (double)(acc[mi][ni][qc]) * (double)sc;
                double v2 = (double)(acc[mi][ni][qc + 2]) * (double)sc;
                s += v1 + v2;
                q += v1 * v1 + v2 * v2;
            }
            csum[ni][qc] = s; csq[ni][qc] = q;
        }
    // reduce across gid lanes (lane bits 2..4) in FP64
#pragma unroll
    for (int off = 4; off <= 16; off <<= 1) {
#pragma unroll
        for (int ni = 0; ni < 4; ni++)
#pragma unroll
            for (int qc = 0; qc < 2; qc++) {
                csum[ni][qc] += __shfl_xor_sync(0xffffffffu, csum[ni][qc], off);
                csq[ni][qc]  += __shfl_xor_sync(0xffffffffu, csq[ni][qc], off);
            }
    }
    __syncthreads();                 // all LDSM done; safe to reuse stage smem
    double* scs = (double*)smem;     // [2][128]
    double* scq = scs + 256;         // [2][128]
    if (gid == 0) {
#pragma unroll
        for (int ni = 0; ni < 4; ni++)
#pragma unroll
            for (int qc = 0; qc < 2; qc++) {
                int cl = wn + ni * 8 + tig * 2 + qc;
                scs[(wid & 1) * 128 + cl] = csum[ni][qc];
                scq[(wid & 1) * 128 + cl] = csq[ni][qc];
            }
    }
    __syncthreads();
    if (tid < 128) {
        int mt = blockIdx.x;
        g_psum[(size_t)mt * N + n0 + tid]   = scs[tid] + scs[128 + tid];
        g_psumsq[(size_t)mt * N + n0 + tid] = scq[tid] + scq[128 + tid];
    }
}

// ---------------------------------------------------------------------------
// Column stats finalize: sum per-mtile fp64 partials, build scale/bias
// ---------------------------------------------------------------------------
__global__ void stats_final_kernel(const float* __restrict__ gamma,
                                   const float* __restrict__ beta,
                                   int Bsz, int C, int nslot) {
    int c = blockIdx.x * blockDim.x + threadIdx.x;
    if (c >= C) return;
    double s = 0, q = 0;
    for (int i = 0; i < nslot; i++) {
        s += g_psum[(size_t)i * C + c];
        q += g_psumsq[(size_t)i * C + c];
    }
    double mean = s / (double)Bsz;
    double var = q / (double)Bsz - mean * mean;
    double inv = 1.0 / sqrt(var + 1e-5);
    float sc = (float)((double)gamma[c] * inv);
    g_scale[c] = sc;
    g_bias[c] = beta[c] - (float)mean * sc;
}

// ---------------------------------------------------------------------------
// Per-row: BN+ReLU(approx h16) -> radix top-(k+32) candidates -> exact serial
// ascending-k fp32 FMA refinement -> exact rank/top-k -> sparse decode.
// ---------------------------------------------------------------------------
__global__ __launch_bounds__(256) void topk_refine_decode_kernel(
    const float* __restrict__ x, const float* __restrict__ W_enc,
    const float* __restrict__ b_dec, const int* __restrict__ topk_p,
    float* __restrict__ out, int C, int D) {
    extern __shared__ float sm[];
    float* vals = sm;                          // C floats (radix phase)
    unsigned* hist = (unsigned*)(vals + C);    // 2048
    unsigned* chunks = hist + 2048;            // 256
    float* xrow = sm;                          // reuse after selection (D floats)

    __shared__ int s_selIdx[NCAND];
    __shared__ float s_exVal[NCAND];
    __shared__ int s_fIdx[128];
    __shared__ float s_fVal[128];
    __shared__ int s_eqIdx[256];
    __shared__ int s_nsel, s_neq, s_need, s_chunk, s_flagzero;
    __shared__ unsigned s_prefix;

    int row = blockIdx.x;
    int tid = threadIdx.x;
    int k = *topk_p;
    if (k > C) k = C;
    if (k > 128) k = 128;                      // problem uses 64
    int kc = k + 32;                           // candidate margin
    if (kc > C) kc = C;
    if (kc > NCAND) kc = NCAND;

    for (int c = tid; c < C; c += 256) {
        float v = __half2float(g_h16[(size_t)row * C + c]);
        v = v * g_scale[c] + g_bias[c];
        vals[c] = (v > 0.f) ? v : 0.f;
    }
    if (tid == 0) { s_nsel = 0; s_neq = 0; s_need = kc; s_prefix = 0u; s_flagzero = 0; }
    __syncthreads();

    // ---- exact radix threshold for kc-th approx value ----
    {
        const int shifts[3] = {21, 10, 0};
        const int nbitsA[3] = {11, 11, 10};
        const unsigned maskHi[3] = {0u, 0xFFE00000u, 0xFFFFFC00u};

        for (int r = 0; r < 3; r++) {
            int nb = 1 << nbitsA[r];
            for (int i = tid; i < nb; i += 256) hist[i] = 0u;
            __syncthreads();

            unsigned pre = s_prefix, mh = maskHi[r], msk = (unsigned)(nb - 1);
            int sh = shifts[r];
            for (int c = tid; c < C; c += 256) {
                unsigned key = __float_as_uint(vals[c]);
                if (key != 0u && (key & mh) == pre)
                    atomicAdd(&hist[(key >> sh) & msk], 1u);
            }
            __syncthreads();

            int NCH = nb >> 3;
            unsigned csum = 0u;
            if (tid < NCH) {
#pragma unroll
                for (int j = 0; j < 8; j++) csum += hist[tid * 8 + j];
                chunks[tid] = csum;
            }
            __syncthreads();
            for (int off = 1; off < NCH; off <<= 1) {
                unsigned add = 0u;
                if (tid < NCH && tid + off < NCH) add = chunks[tid + off];
                __syncthreads();
                if (tid < NCH) chunks[tid] += add;
                __syncthreads();
            }

            int need = s_need;
            if (tid < NCH) {
                int incl = (int)chunks[tid];
                int excl = incl - (int)csum;
                if (excl < need && incl >= need) s_chunk = tid;
                if (tid == 0 && incl < need) s_flagzero = 1;
            }
            __syncthreads();
            if (s_flagzero) break;

            if (tid == 0) {
                int t = s_chunk;
                unsigned cs = 0u;
#pragma unroll
                for (int j = 0; j < 8; j++) cs += hist[t * 8 + j];
                int cum = (int)chunks[t] - (int)cs;
                for (int j = 7; j >= 0; j--) {
                    int hc = (int)hist[t * 8 + j];
                    cum += hc;
                    if (cum >= need) {
                        s_prefix |= ((unsigned)(t * 8 + j)) << sh;
                        s_need = need - (cum - hc);
                        break;
                    }
                }
            }
            __syncthreads();
        }
        __syncthreads();

        unsigned T = s_prefix;
        int need_eq = s_need;
        bool zeroThresh = (s_flagzero != 0);

        for (int c = tid; c < C; c += 256) {
            unsigned key = __float_as_uint(vals[c]);
            if (key == 0u) continue;
            if (zeroThresh || key > T) {
                int p = atomicAdd(&s_nsel, 1);
                if (p < NCAND) s_selIdx[p] = c;
            } else if (key == T) {
                int p = atomicAdd(&s_neq, 1);
                if (p < 256) s_eqIdx[p] = c;
            }
        }
        __syncthreads();

        if (!zeroThresh && tid == 0) {
            int ne = s_neq; if (ne > 256) ne = 256;
            for (int i = 1; i < ne; i++) {
                int v = s_eqIdx[i]; int j = i - 1;
                while (j >= 0 && s_eqIdx[j] > v) { s_eqIdx[j + 1] = s_eqIdx[j]; j--; }
                s_eqIdx[j + 1] = v;
            }
            int take = need_eq; if (take > ne) take = ne;
            int base = s_nsel;
            for (int i = 0; i < take; i++) {
                int p = base + i;
                if (p < NCAND) s_selIdx[p] = s_eqIdx[i];
            }
            s_nsel = base + take;
        }
        __syncthreads();
    }

    int ncand = s_nsel; if (ncand > NCAND) ncand = NCAND;
    int myc = (tid < ncand) ? s_selIdx[tid] : -1;
    __syncthreads();

    for (int d = tid; d < D; d += 256) xrow[d] = x[(size_t)row * D + d];
    __syncthreads();

    // ---- exact serial ascending-k FMA dot per candidate (R1/R4/R6-proven) ----
    float facc = 0.f;
    if (myc >= 0) {
        const float4* wr = (const float4*)(W_enc + (size_t)myc * D);
        const int NIT = D >> 2;
        float4 buf[16];
#pragma unroll
        for (int p = 0; p < 16; p++) buf[p] = wr[p];
        for (int i = 0; i < NIT; i++) {
            float4 w = buf[i & 15];
            int pi = i + 16;
            if (pi < NIT) buf[i & 15] = wr[pi];
            const float* xq = &xrow[i << 2];
            facc = __fmaf_rn(xq[0], w.x, facc);
            facc = __fmaf_rn(xq[1], w.y, facc);
            facc = __fmaf_rn(xq[2], w.z, facc);
            facc = __fmaf_rn(xq[3], w.w, facc);
        }
        float bn = __fmaf_rn(facc, g_scale[myc], g_bias[myc]);
        s_exVal[tid] = (bn > 0.f) ? bn : 0.f;
    }
    __syncthreads();

    // ---- exact rank (value desc, index asc) and top-k selection ----
    int kk = (k < ncand) ? k : ncand;
    if (tid < ncand) {
        float vj = s_exVal[tid]; int cj = myc;
        int rank = 0;
        for (int i = 0; i < ncand; i++) {
            float vi = s_exVal[i]; int ci = s_selIdx[i];
            if (vi > vj || (vi == vj && ci < cj)) rank++;
        }
        if (rank < kk) { s_fVal[rank] = vj; s_fIdx[rank] = cj; }
    }
    __syncthreads();

    // ---- sparse decode: recon = sum v_j * WnT[c_j,:] + b_dec ----
    for (int dbase = 0; dbase < D; dbase += 1024) {
        int d = dbase + tid * 4;
        if (d + 3 < D) {
            float4 acc = *(const float4*)(b_dec + d);
            for (int j = 0; j < kk; j++) {
                int ci = s_fIdx[j];
                float v = s_fVal[j];
                float4 w = *(const float4*)(&g_WnT[(size_t)ci * D + d]);
                acc.x += v * w.x; acc.y += v * w.y;
                acc.z += v * w.z; acc.w += v * w.w;
            }
            *(float4*)(out + (size_t)row * D + d) = acc;
        }
    }
}

// ---------------------------------------------------------------------------
// Launch
// ---------------------------------------------------------------------------
extern "C" void kernel_launch(void* const* d_in, const int* in_sizes, int n_in,
                              void* d_out, int out_size) {
    const float* x = (const float*)d_in[0];
    const float* W_enc = (const float*)d_in[1];
    const float* gamma = (const float*)d_in[3];
    const float* beta = (const float*)d_in[4];
    const float* W_dec = (const float*)d_in[5];
    const float* b_dec = (const float*)d_in[6];
    const int* topk = (const int*)d_in[7];

    int D = in_sizes[6];          // K
    int C = in_sizes[2];          // N
    int B = in_sizes[0] / D;      // M
    float* out = (float*)d_out;

    int nx = B * D, nw = C * D;
    split_x_kernel<<<(nx + 255) / 256, 256>>>(x, nx);
    split_w_kernel<<<(nw + 255) / 256, 256>>>(W_enc, nw);

    colnorm_kernel<<<(C + 255) / 256, 256>>>(W_dec, D, C);

    dim3 tg((C + 31) / 32, (D + 31) / 32);
    transpose_kernel<<<tg, dim3(32, 8)>>>(W_dec, D, C);

    cudaFuncSetAttribute(hgemm_kernel,
                         cudaFuncAttributeMaxDynamicSharedMemorySize, GEMM_SMEM);
    dim3 gg(B / 128, C / 128);   // m fast -> concurrent CTAs share W tiles in L2
    hgemm_kernel<<<gg, 256, GEMM_SMEM>>>(B, C, D);

    stats_final_kernel<<<(C + 255) / 256, 256>>>(gamma, beta, B, C, B / 128);

    size_t dyn = (size_t)C * sizeof(float) + 2048 * sizeof(unsigned) + 256 * sizeof(unsigned);
    cudaFuncSetAttribute(topk_refine_decode_kernel,
                         cudaFuncAttributeMaxDynamicSharedMemorySize, (int)dyn);
    topk_refine_decode_kernel<<<B, 256, dyn>>>(x, W_enc, b_dec, topk, out, C, D);
}

// round 10
// speedup vs baseline: 1.3630x; 1.0117x over previous
#include <cuda_runtime.h>
#include <cuda_fp16.h>
#include <cstdint>

// B=4096, D(K)=2048, C=16384, topk=64
// recon = TopK(BN(x @ W_enc^T)) @ normalize_cols(W_dec)^T + b_dec
// b_enc cancels inside batch-norm -> skipped everywhere (consistent).
//
// Numerics ledger (R4..R9):
//  - BN stats: fp64 reduction of split-fp16 fp32 GEMM accumulators.
//  - Candidate generation tolerates ~7e-4 value noise -> h stored fp16,
//    margin 16 (>=100 sigma containment).
//  - Refinement MUST be the serial ascending-k fp32 FMA chain (R7/R8 proof).
// R10: launch order puts hgemm at slot 4 (ncu captures #4); margin 32->16.

#define MAX_B 4096
#define MAX_C 16384
#define MAX_D 2048
#define MAX_MT 32            // max M/128 tiles
#define NCAND 160

__device__ __half g_h16[(size_t)MAX_B * MAX_C];     // 128 MB approx pre-BN activations
__device__ float g_WnT[(size_t)MAX_C * MAX_D];      // 128 MB normalized decoder [C,D]
__device__ float g_inv_norm[MAX_C];
__device__ float g_scale[MAX_C];
__device__ float g_bias[MAX_C];
__device__ double g_psum[MAX_MT * MAX_C];           // per-(mtile,col) fp64 partials
__device__ double g_psumsq[MAX_MT * MAX_C];
__device__ __half g_xh[(size_t)MAX_B * MAX_D];
__device__ __half g_xl[(size_t)MAX_B * MAX_D];
__device__ __half g_wh[(size_t)MAX_C * MAX_D];
__device__ __half g_wl[(size_t)MAX_C * MAX_D];

// ---------------------------------------------------------------------------
// fp16 split kernels (power-of-2 pre-scaling keeps residuals normal-range)
// ---------------------------------------------------------------------------
__global__ void split_x_kernel(const float* __restrict__ src, int n) {
    int i = blockIdx.x * blockDim.x + threadIdx.x;
    if (i >= n) return;
    float s = src[i] * 4096.0f;                  // 2^12, exact
    __half h = __float2half_rn(s);
    g_xh[i] = h;
    g_xl[i] = __float2half_rn(s - __half2float(h));
}
__global__ void split_w_kernel(const float* __restrict__ src, int n) {
    int i = blockIdx.x * blockDim.x + threadIdx.x;
    if (i >= n) return;
    float s = src[i] * 262144.0f;                // 2^18, exact
    __half h = __float2half_rn(s);
    g_wh[i] = h;
    g_wl[i] = __float2half_rn(s - __half2float(h));
}

// ---------------------------------------------------------------------------
// W_dec column inv-norms (fp64)
// ---------------------------------------------------------------------------
__global__ void colnorm_kernel(const float* __restrict__ Wdec, int D, int C) {
    int c = blockIdx.x * blockDim.x + threadIdx.x;
    if (c >= C) return;
    double s0 = 0, s1 = 0, s2 = 0, s3 = 0;
    int d = 0;
    for (; d + 3 < D; d += 4) {
        float w0 = Wdec[(size_t)(d + 0) * C + c];
        float w1 = Wdec[(size_t)(d + 1) * C + c];
        float w2 = Wdec[(size_t)(d + 2) * C + c];
        float w3 = Wdec[(size_t)(d + 3) * C + c];
        s0 += (double)w0 * w0; s1 += (double)w1 * w1;
        s2 += (double)w2 * w2; s3 += (double)w3 * w3;
    }
    for (; d < D; d++) { float w = Wdec[(size_t)d * C + c]; s0 += (double)w * w; }
    double n = sqrt(s0 + s1 + s2 + s3);
    if (n < 1e-12) n = 1e-12;
    g_inv_norm[c] = (float)(1.0 / n);
}

// ---------------------------------------------------------------------------
// Transpose + scale: WnT[c,d] = W_dec[d,c] * inv_norm[c]
// ---------------------------------------------------------------------------
__global__ void transpose_kernel(const float* __restrict__ Wdec, int D, int C) {
    __shared__ float tile[32][33];
    int c0 = blockIdx.x * 32, d0 = blockIdx.y * 32;
    for (int i = threadIdx.y; i < 32; i += 8) {
        int d = d0 + i, c = c0 + threadIdx.x;
        tile[i][threadIdx.x] = (d < D && c < C) ? Wdec[(size_t)d * C + c] : 0.f;
    }
    __syncthreads();
    for (int i = threadIdx.y; i < 32; i += 8) {
        int c = c0 + i, d = d0 + threadIdx.x;
        if (c < C && d < D)
            g_WnT[(size_t)c * D + d] = tile[threadIdx.x][i] * g_inv_norm[c];
    }
}

// ---------------------------------------------------------------------------
// mma.sync split-fp16 GEMM: 128x128 tile, BK=32, 3 stages, SW64, 2 CTAs/SM.
// Inner loop: product-outer ordering (acc reuse distance 4).
// Epilogue: h16 store + fused per-CTA column sum/sumsq partials in FP64.
// ---------------------------------------------------------------------------
#define BKH 32
#define MAT_BYTES 8192           // 128 rows x 32 halves x 2B
#define STAGE_BYTES 32768        // 4 matrices
#define STAGES 3
#define GEMM_SMEM (STAGES * STAGE_BYTES)

#define LDSM4(R0, R1, R2, R3, ADDR) \
    asm volatile("ldmatrix.sync.aligned.m8n8.x4.shared.b16 {%0,%1,%2,%3}, [%4];" \
                 : "=r"(R0), "=r"(R1), "=r"(R2), "=r"(R3) : "r"(ADDR))

#define MMA16816(CC, A0, A1, A2, A3, B0, B1) \
    asm volatile("mma.sync.aligned.m16n8k16.row.col.f32.f16.f16.f32 " \
                 "{%0,%1,%2,%3}, {%4,%5,%6,%7}, {%8,%9}, {%0,%1,%2,%3};" \
                 : "+f"((CC)[0]), "+f"((CC)[1]), "+f"((CC)[2]), "+f"((CC)[3]) \
                 : "r"(A0), "r"(A1), "r"(A2), "r"(A3), "r"(B0), "r"(B1))

__device__ __forceinline__ uint32_t smem_u32(const void* p) {
    uint32_t a;
    asm("{ .reg .u64 t; cvta.to.shared.u64 t, %1; cvt.u32.u64 %0, t; }" : "=r"(a) : "l"(p));
    return a;
}
__device__ __forceinline__ uint32_t swz64(uint32_t base, int row, int kbyte) {
    uint32_t off = row * 64 + kbyte;
    return base + (off ^ ((off >> 3) & 0x30));
}
__device__ __forceinline__ void cpasync16(uint32_t sa, const void* g) {
    asm volatile("cp.async.cg.shared.global [%0], [%1], 16;" :: "r"(sa), "l"(g));
}

__device__ __forceinline__ void load_stage(uint32_t sbase, int m0, int n0,
                                           int k0, int K, int tid) {
    const __half* srcs[4] = {g_xh, g_xl, g_wh, g_wl};
    int r0s[4] = {m0, m0, n0, n0};
#pragma unroll
    for (int mat = 0; mat < 4; mat++) {
        const __half* src = srcs[mat];
        int r0 = r0s[mat];
#pragma unroll
        for (int s = 0; s < 2; s++) {
            int idx = tid * 2 + s;             // 0..511
            int row = idx >> 2, seg = idx & 3; // 128 rows x 4 16B-segments
            const __half* g = src + (size_t)(r0 + row) * K + k0 + seg * 8;
            cpasync16(swz64(sbase + mat * MAT_BYTES, row, seg * 16), g);
        }
    }
}

__global__ __launch_bounds__(256, 2)
void hgemm_kernel(int M, int N, int K) {
    extern __shared__ __align__(1024) char smem[];
    const uint32_t sb = smem_u32(smem);
    const int tid = threadIdx.x;
    const int wid = tid >> 5, lane = tid & 31;
    const int wm = (wid & 1) * 64;      // warp tile 64 (M) x 32 (N)
    const int wn = (wid >> 1) * 32;
    const int m0 = blockIdx.x * 128;
    const int n0 = blockIdx.y * 128;
    const int grp = lane >> 3, lr = lane & 7;
    const int NK = K / BKH;

    float acc[4][4][4];
#pragma unroll
    for (int i = 0; i < 4; i++)
#pragma unroll
        for (int j = 0; j < 4; j++)
#pragma unroll
            for (int q = 0; q < 4; q++) acc[i][j][q] = 0.f;

#pragma unroll
    for (int s = 0; s < STAGES - 1; s++) {
        load_stage(sb + s * STAGE_BYTES, m0, n0, s * BKH, K, tid);
        asm volatile("cp.async.commit_group;");
    }

    for (int ch = 0; ch < NK; ch++) {
        asm volatile("cp.async.wait_group %0;" :: "n"(STAGES - 2));
        __syncthreads();

        int pf = ch + STAGES - 1;
        if (pf < NK)
            load_stage(sb + (pf % STAGES) * STAGE_BYTES, m0, n0, pf * BKH, K, tid);
        asm volatile("cp.async.commit_group;");

        uint32_t sa = sb + (ch % STAGES) * STAGE_BYTES;
        uint32_t aH = sa, aL = sa + MAT_BYTES;
        uint32_t bH = sa + 2 * MAT_BYTES, bL = sa + 3 * MAT_BYTES;

#pragma unroll
        for (int ks = 0; ks < 2; ks++) {
            int kb = ks * 32;
            uint32_t Bh[4][2], Bl[4][2];
#pragma unroll
            for (int np = 0; np < 2; np++) {
                int nrow = wn + np * 16 + (grp >> 1) * 8 + lr;
                int kbyte = kb + (grp & 1) * 16;
                uint32_t r0, r1, r2, r3;
                LDSM4(r0, r1, r2, r3, swz64(bH, nrow, kbyte));
                Bh[np * 2][0] = r0; Bh[np * 2][1] = r1;
                Bh[np * 2 + 1][0] = r2; Bh[np * 2 + 1][1] = r3;
                LDSM4(r0, r1, r2, r3, swz64(bL, nrow, kbyte));
                Bl[np * 2][0] = r0; Bl[np * 2][1] = r1;
                Bl[np * 2 + 1][0] = r2; Bl[np * 2 + 1][1] = r3;
            }
#pragma unroll
            for (int mi = 0; mi < 4; mi++) {
                int arow = wm + mi * 16 + (grp & 1) * 8 + lr;
                int kbyte = kb + (grp >> 1) * 16;
                uint32_t a0, a1, a2, a3, l0, l1, l2, l3;
                LDSM4(a0, a1, a2, a3, swz64(aH, arow, kbyte));
                LDSM4(l0, l1, l2, l3, swz64(aL, arow, kbyte));
                // product-outer: same-acc reuse distance = 4 mmas
#pragma unroll
                for (int ni = 0; ni < 4; ni++)
                    MMA16816(acc[mi][ni], a0, a1, a2, a3, Bh[ni][0], Bh[ni][1]);
#pragma unroll
                for (int ni = 0; ni < 4; ni++)
                    MMA16816(acc[mi][ni], a0, a1, a2, a3, Bl[ni][0], Bl[ni][1]);
#pragma unroll
                for (int ni = 0; ni < 4; ni++)
                    MMA16816(acc[mi][ni], l0, l1, l2, l3, Bh[ni][0], Bh[ni][1]);
            }
        }
        __syncthreads();
    }

    // ---- epilogue: h16 store + fused column stats partials (FP64) ----
    const float sc = 9.313225746154785e-10f;  // 2^-30
    int gid = lane >> 2, tig = lane & 3;
#pragma unroll
    for (int mi = 0; mi < 4; mi++) {
#pragma unroll
        for (int ni = 0; ni < 4; ni++) {
            int r = m0 + wm + mi * 16 + gid;
            int c = n0 + wn + ni * 8 + tig * 2;
            *(__half2*)&g_h16[(size_t)r * N + c] =
                __floats2half2_rn(acc[mi][ni][0] * sc, acc[mi][ni][1] * sc);
            *(__half2*)&g_h16[(size_t)(r + 8) * N + c] =
                __floats2half2_rn(acc[mi][ni][2] * sc, acc[mi][ni][3] * sc);
        }
    }

    // per-thread column partials over its 8 rows (4 mi x 2), 8 columns — FP64
    double csum[4][2], csq[4][2];
#pragma unroll
    for (int ni = 0; ni < 4; ni++)
#pragma unroll
        for (int qc = 0; qc < 2; qc++) {
            double s = 0.0, q = 0.0;
#pragma unroll
            for (int mi = 0; mi < 4; mi++) {
                double v1 = (double)(acc[mi][ni][qc]) * (double)sc;
                double v2 = (double)(acc[mi][ni][qc + 2]) * (double)sc;
                s += v1 + v2;
                q += v1 * v1 + v2 * v2;
            }
            csum[ni][qc] = s; csq[ni][qc] = q;
        }
    // reduce across gid lanes (lane bits 2..4) in FP64
#pragma unroll
    for (int off = 4; off <= 16; off <<= 1) {
#pragma unroll
        for (int ni = 0; ni < 4; ni++)
#pragma unroll
            for (int qc = 0; qc < 2; qc++) {
                csum[ni][qc] += __shfl_xor_sync(0xffffffffu, csum[ni][qc], off);
                csq[ni][qc]  += __shfl_xor_sync(0xffffffffu, csq[ni][qc], off);
            }
    }
    __syncthreads();                 // all LDSM done; safe to reuse stage smem
    double* scs = (double*)smem;     // [2][128]
    double* scq = scs + 256;         // [2][128]
    if (gid == 0) {
#pragma unroll
        for (int ni = 0; ni < 4; ni++)
#pragma unroll
            for (int qc = 0; qc < 2; qc++) {
                int cl = wn + ni * 8 + tig * 2 + qc;
                scs[(wid & 1) * 128 + cl] = csum[ni][qc];
                scq[(wid & 1) * 128 + cl] = csq[ni][qc];
            }
    }
    __syncthreads();
    if (tid < 128) {
        int mt = blockIdx.x;
        g_psum[(size_t)mt * N + n0 + tid]   = scs[tid] + scs[128 + tid];
        g_psumsq[(size_t)mt * N + n0 + tid] = scq[tid] + scq[128 + tid];
    }
}

// ---------------------------------------------------------------------------
// Column stats finalize: sum per-mtile fp64 partials, build scale/bias
// ---------------------------------------------------------------------------
__global__ void stats_final_kernel(const float* __restrict__ gamma,
                                   const float* __restrict__ beta,
                                   int Bsz, int C, int nslot) {
    int c = blockIdx.x * blockDim.x + threadIdx.x;
    if (c >= C) return;
    double s = 0, q = 0;
    for (int i = 0; i < nslot; i++) {
        s += g_psum[(size_t)i * C + c];
        q += g_psumsq[(size_t)i * C + c];
    }
    double mean = s / (double)Bsz;
    double var = q / (double)Bsz - mean * mean;
    double inv = 1.0 / sqrt(var + 1e-5);
    float sc = (float)((double)gamma[c] * inv);
    g_scale[c] = sc;
    g_bias[c] = beta[c] - (float)mean * sc;
}

// ---------------------------------------------------------------------------
// Per-row: BN+ReLU(approx h16) -> radix top-(k+16) candidates -> exact serial
// ascending-k fp32 FMA refinement -> exact rank/top-k -> sparse decode.
// ---------------------------------------------------------------------------
__global__ __launch_bounds__(256) void topk_refine_decode_kernel(
    const float* __restrict__ x, const float* __restrict__ W_enc,
    const float* __restrict__ b_dec, const int* __restrict__ topk_p,
    float* __restrict__ out, int C, int D) {
    extern __shared__ float sm[];
    float* vals = sm;                          // C floats (radix phase)
    unsigned* hist = (unsigned*)(vals + C);    // 2048
    unsigned* chunks = hist + 2048;            // 256
    float* xrow = sm;                          // reuse after selection (D floats)

    __shared__ int s_selIdx[NCAND];
    __shared__ float s_exVal[NCAND];
    __shared__ int s_fIdx[128];
    __shared__ float s_fVal[128];
    __shared__ int s_eqIdx[256];
    __shared__ int s_nsel, s_neq, s_need, s_chunk, s_flagzero;
    __shared__ unsigned s_prefix;

    int row = blockIdx.x;
    int tid = threadIdx.x;
    int k = *topk_p;
    if (k > C) k = C;
    if (k > 128) k = 128;                      // problem uses 64
    int kc = k + 16;                           // candidate margin (>=100 sigma)
    if (kc > C) kc = C;
    if (kc > NCAND) kc = NCAND;

    for (int c = tid; c < C; c += 256) {
        float v = __half2float(g_h16[(size_t)row * C + c]);
        v = v * g_scale[c] + g_bias[c];
        vals[c] = (v > 0.f) ? v : 0.f;
    }
    if (tid == 0) { s_nsel = 0; s_neq = 0; s_need = kc; s_prefix = 0u; s_flagzero = 0; }
    __syncthreads();

    // ---- exact radix threshold for kc-th approx value ----
    {
        const int shifts[3] = {21, 10, 0};
        const int nbitsA[3] = {11, 11, 10};
        const unsigned maskHi[3] = {0u, 0xFFE00000u, 0xFFFFFC00u};

        for (int r = 0; r < 3; r++) {
            int nb = 1 << nbitsA[r];
            for (int i = tid; i < nb; i += 256) hist[i] = 0u;
            __syncthreads();

            unsigned pre = s_prefix, mh = maskHi[r], msk = (unsigned)(nb - 1);
            int sh = shifts[r];
            for (int c = tid; c < C; c += 256) {
                unsigned key = __float_as_uint(vals[c]);
                if (key != 0u && (key & mh) == pre)
                    atomicAdd(&hist[(key >> sh) & msk], 1u);
            }
            __syncthreads();

            int NCH = nb >> 3;
            unsigned csum = 0u;
            if (tid < NCH) {
#pragma unroll
                for (int j = 0; j < 8; j++) csum += hist[tid * 8 + j];
                chunks[tid] = csum;
            }
            __syncthreads();
            for (int off = 1; off < NCH; off <<= 1) {
                unsigned add = 0u;
                if (tid < NCH && tid + off < NCH) add = chunks[tid + off];
                __syncthreads();
                if (tid < NCH) chunks[tid] += add;
                __syncthreads();
            }

            int need = s_need;
            if (tid < NCH) {
                int incl = (int)chunks[tid];
                int excl = incl - (int)csum;
                if (excl < need && incl >= need) s_chunk = tid;
                if (tid == 0 && incl < need) s_flagzero = 1;
            }
            __syncthreads();
            if (s_flagzero) break;

            if (tid == 0) {
                int t = s_chunk;
                unsigned cs = 0u;
#pragma unroll
                for (int j = 0; j < 8; j++) cs += hist[t * 8 + j];
                int cum = (int)chunks[t] - (int)cs;
                for (int j = 7; j >= 0; j--) {
                    int hc = (int)hist[t * 8 + j];
                    cum += hc;
                    if (cum >= need) {
                        s_prefix |= ((unsigned)(t * 8 + j)) << sh;
                        s_need = need - (cum - hc);
                        break;
                    }
                }
            }
            __syncthreads();
        }
        __syncthreads();

        unsigned T = s_prefix;
        int need_eq = s_need;
        bool zeroThresh = (s_flagzero != 0);

        for (int c = tid; c < C; c += 256) {
            unsigned key = __float_as_uint(vals[c]);
            if (key == 0u) continue;
            if (zeroThresh || key > T) {
                int p = atomicAdd(&s_nsel, 1);
                if (p < NCAND) s_selIdx[p] = c;
            } else if (key == T) {
                int p = atomicAdd(&s_neq, 1);
                if (p < 256) s_eqIdx[p] = c;
            }
        }
        __syncthreads();

        if (!zeroThresh && tid == 0) {
            int ne = s_neq; if (ne > 256) ne = 256;
            for (int i = 1; i < ne; i++) {
                int v = s_eqIdx[i]; int j = i - 1;
                while (j >= 0 && s_eqIdx[j] > v) { s_eqIdx[j + 1] = s_eqIdx[j]; j--; }
                s_eqIdx[j + 1] = v;
            }
            int take = need_eq; if (take > ne) take = ne;
            int base = s_nsel;
            for (int i = 0; i < take; i++) {
                int p = base + i;
                if (p < NCAND) s_selIdx[p] = s_eqIdx[i];
            }
            s_nsel = base + take;
        }
        __syncthreads();
    }

    int ncand = s_nsel; if (ncand > NCAND) ncand = NCAND;
    int myc = (tid < ncand) ? s_selIdx[tid] : -1;
    __syncthreads();

    for (int d = tid; d < D; d += 256) xrow[d] = x[(size_t)row * D + d];
    __syncthreads();

    // ---- exact serial ascending-k FMA dot per candidate (R1/R4/R6-proven) ----
    float facc = 0.f;
    if (myc >= 0) {
        const float4* wr = (const float4*)(W_enc + (size_t)myc * D);
        const int NIT = D >> 2;
        float4 buf[16];
#pragma unroll
        for (int p = 0; p < 16; p++) buf[p] = wr[p];
        for (int i = 0; i < NIT; i++) {
            float4 w = buf[i & 15];
            int pi = i + 16;
            if (pi < NIT) buf[i & 15] = wr[pi];
            const float* xq = &xrow[i << 2];
            facc = __fmaf_rn(xq[0], w.x, facc);
            facc = __fmaf_rn(xq[1], w.y, facc);
            facc = __fmaf_rn(xq[2], w.z, facc);
            facc = __fmaf_rn(xq[3], w.w, facc);
        }
        float bn = __fmaf_rn(facc, g_scale[myc], g_bias[myc]);
        s_exVal[tid] = (bn > 0.f) ? bn : 0.f;
    }
    __syncthreads();

    // ---- exact rank (value desc, index asc) and top-k selection ----
    int kk = (k < ncand) ? k : ncand;
    if (tid < ncand) {
        float vj = s_exVal[tid]; int cj = myc;
        int rank = 0;
        for (int i = 0; i < ncand; i++) {
            float vi = s_exVal[i]; int ci = s_selIdx[i];
            if (vi > vj || (vi == vj && ci < cj)) rank++;
        }
        if (rank < kk) { s_fVal[rank] = vj; s_fIdx[rank] = cj; }
    }
    __syncthreads();

    // ---- sparse decode: recon = sum v_j * WnT[c_j,:] + b_dec ----
    for (int dbase = 0; dbase < D; dbase += 1024) {
        int d = dbase + tid * 4;
        if (d + 3 < D) {
            float4 acc = *(const float4*)(b_dec + d);
            for (int j = 0; j < kk; j++) {
                int ci = s_fIdx[j];
                float v = s_fVal[j];
                float4 w = *(const float4*)(&g_WnT[(size_t)ci * D + d]);
                acc.x += v * w.x; acc.y += v * w.y;
                acc.z += v * w.z; acc.w += v * w.w;
            }
            *(float4*)(out + (size_t)row * D + d) = acc;
        }
    }
}

// ---------------------------------------------------------------------------
// Launch — hgemm deliberately placed as 4th launch (ncu captures #4)
// ---------------------------------------------------------------------------
extern "C" void kernel_launch(void* const* d_in, const int* in_sizes, int n_in,
                              void* d_out, int out_size) {
    const float* x = (const float*)d_in[0];
    const float* W_enc = (const float*)d_in[1];
    const float* gamma = (const float*)d_in[3];
    const float* beta = (const float*)d_in[4];
    const float* W_dec = (const float*)d_in[5];
    const float* b_dec = (const float*)d_in[6];
    const int* topk = (const int*)d_in[7];

    int D = in_sizes[6];          // K
    int C = in_sizes[2];          // N
    int B = in_sizes[0] / D;      // M
    float* out = (float*)d_out;

    int nx = B * D, nw = C * D;
    split_x_kernel<<<(nx + 255) / 256, 256>>>(x, nx);          // #1
    split_w_kernel<<<(nw + 255) / 256, 256>>>(W_enc, nw);      // #2
    colnorm_kernel<<<(C + 255) / 256, 256>>>(W_dec, D, C);     // #3

    cudaFuncSetAttribute(hgemm_kernel,
                         cudaFuncAttributeMaxDynamicSharedMemorySize, GEMM_SMEM);
    dim3 gg(B / 128, C / 128);   // m fast -> concurrent CTAs share W tiles in L2
    hgemm_kernel<<<gg, 256, GEMM_SMEM>>>(B, C, D);             // #4 (profiled)

    dim3 tg((C + 31) / 32, (D + 31) / 32);
    transpose_kernel<<<tg, dim3(32, 8)>>>(W_dec, D, C);        // #5

    stats_final_kernel<<<(C + 255) / 256, 256>>>(gamma, beta, B, C, B / 128);  // #6

    size_t dyn = (size_t)C * sizeof(float) + 2048 * sizeof(unsigned) + 256 * sizeof(unsigned);
    cudaFuncSetAttribute(topk_refine_decode_kernel,
                         cudaFuncAttributeMaxDynamicSharedMemorySize, (int)dyn);
    topk_refine_decode_kernel<<<B, 256, dyn>>>(x, W_enc, b_dec, topk, out, C, D);  // #7
}

// round 11
// speedup vs baseline: 2.0975x; 1.5389x over previous
#include <cuda_runtime.h>
#include <cuda_fp16.h>
#include <cstdint>

// B=4096, D(K)=2048, C=16384, topk=64
// recon = TopK(BN(x @ W_enc^T)) @ normalize_cols(W_dec)^T + b_dec
// b_enc cancels inside batch-norm -> skipped everywhere (consistent).
//
// Numerics ledger (R4..R10):
//  - BN stats: fp64 reduction of split-fp16 fp32 GEMM accumulators.
//  - Candidate generation tolerates ~7e-4 value noise -> h stored fp16,
//    margin 16 (>=100 sigma containment).
//  - Refinement MUST be the serial ascending-k fp32 FMA chain (R7/R8 proof).
//    (Load scheduling may change; the facc FMA sequence may not.)
// R11: topk split into select (74KB smem) + refine_decode (12KB smem, high
// occupancy); split kernels fused so topk_select is profiled at slot #4.

#define MAX_B 4096
#define MAX_C 16384
#define MAX_D 2048
#define MAX_MT 32
#define NCAND 160

__device__ __half g_h16[(size_t)MAX_B * MAX_C];     // 128 MB approx pre-BN activations
__device__ float g_WnT[(size_t)MAX_C * MAX_D];      // 128 MB normalized decoder [C,D]
__device__ float g_inv_norm[MAX_C];
__device__ float g_scale[MAX_C];
__device__ float g_bias[MAX_C];
__device__ double g_psum[MAX_MT * MAX_C];
__device__ double g_psumsq[MAX_MT * MAX_C];
__device__ __half g_xh[(size_t)MAX_B * MAX_D];
__device__ __half g_xl[(size_t)MAX_B * MAX_D];
__device__ __half g_wh[(size_t)MAX_C * MAX_D];
__device__ __half g_wl[(size_t)MAX_C * MAX_D];
__device__ int g_candIdx[(size_t)MAX_B * NCAND];
__device__ int g_candCnt[MAX_B];

// ---------------------------------------------------------------------------
// Fused fp16 split (x and W in one launch)
// ---------------------------------------------------------------------------
__global__ void split_all_kernel(const float* __restrict__ x,
                                 const float* __restrict__ W, int nx, int nw) {
    int i = blockIdx.x * blockDim.x + threadIdx.x;
    if (i < nx) {
        float s = x[i] * 4096.0f;                // 2^12, exact
        __half h = __float2half_rn(s);
        g_xh[i] = h;
        g_xl[i] = __float2half_rn(s - __half2float(h));
    } else if (i < nx + nw) {
        int j = i - nx;
        float s = W[j] * 262144.0f;              // 2^18, exact
        __half h = __float2half_rn(s);
        g_wh[j] = h;
        g_wl[j] = __float2half_rn(s - __half2float(h));
    }
}

// ---------------------------------------------------------------------------
// W_dec column inv-norms (fp64)
// ---------------------------------------------------------------------------
__global__ void colnorm_kernel(const float* __restrict__ Wdec, int D, int C) {
    int c = blockIdx.x * blockDim.x + threadIdx.x;
    if (c >= C) return;
    double s0 = 0, s1 = 0, s2 = 0, s3 = 0;
    int d = 0;
    for (; d + 3 < D; d += 4) {
        float w0 = Wdec[(size_t)(d + 0) * C + c];
        float w1 = Wdec[(size_t)(d + 1) * C + c];
        float w2 = Wdec[(size_t)(d + 2) * C + c];
        float w3 = Wdec[(size_t)(d + 3) * C + c];
        s0 += (double)w0 * w0; s1 += (double)w1 * w1;
        s2 += (double)w2 * w2; s3 += (double)w3 * w3;
    }
    for (; d < D; d++) { float w = Wdec[(size_t)d * C + c]; s0 += (double)w * w; }
    double n = sqrt(s0 + s1 + s2 + s3);
    if (n < 1e-12) n = 1e-12;
    g_inv_norm[c] = (float)(1.0 / n);
}

// ---------------------------------------------------------------------------
// Transpose + scale: WnT[c,d] = W_dec[d,c] * inv_norm[c]
// ---------------------------------------------------------------------------
__global__ void transpose_kernel(const float* __restrict__ Wdec, int D, int C) {
    __shared__ float tile[32][33];
    int c0 = blockIdx.x * 32, d0 = blockIdx.y * 32;
    for (int i = threadIdx.y; i < 32; i += 8) {
        int d = d0 + i, c = c0 + threadIdx.x;
        tile[i][threadIdx.x] = (d < D && c < C) ? Wdec[(size_t)d * C + c] : 0.f;
    }
    __syncthreads();
    for (int i = threadIdx.y; i < 32; i += 8) {
        int c = c0 + i, d = d0 + threadIdx.x;
        if (c < C && d < D)
            g_WnT[(size_t)c * D + d] = tile[threadIdx.x][i] * g_inv_norm[c];
    }
}

// ---------------------------------------------------------------------------
// mma.sync split-fp16 GEMM (unchanged from R10; 62.7% tensor measured)
// ---------------------------------------------------------------------------
#define BKH 32
#define MAT_BYTES 8192
#define STAGE_BYTES 32768
#define STAGES 3
#define GEMM_SMEM (STAGES * STAGE_BYTES)

#define LDSM4(R0, R1, R2, R3, ADDR) \
    asm volatile("ldmatrix.sync.aligned.m8n8.x4.shared.b16 {%0,%1,%2,%3}, [%4];" \
                 : "=r"(R0), "=r"(R1), "=r"(R2), "=r"(R3) : "r"(ADDR))

#define MMA16816(CC, A0, A1, A2, A3, B0, B1) \
    asm volatile("mma.sync.aligned.m16n8k16.row.col.f32.f16.f16.f32 " \
                 "{%0,%1,%2,%3}, {%4,%5,%6,%7}, {%8,%9}, {%0,%1,%2,%3};" \
                 : "+f"((CC)[0]), "+f"((CC)[1]), "+f"((CC)[2]), "+f"((CC)[3]) \
                 : "r"(A0), "r"(A1), "r"(A2), "r"(A3), "r"(B0), "r"(B1))

__device__ __forceinline__ uint32_t smem_u32(const void* p) {
    uint32_t a;
    asm("{ .reg .u64 t; cvta.to.shared.u64 t, %1; cvt.u32.u64 %0, t; }" : "=r"(a) : "l"(p));
    return a;
}
__device__ __forceinline__ uint32_t swz64(uint32_t base, int row, int kbyte) {
    uint32_t off = row * 64 + kbyte;
    return base + (off ^ ((off >> 3) & 0x30));
}
__device__ __forceinline__ void cpasync16(uint32_t sa, const void* g) {
    asm volatile("cp.async.cg.shared.global [%0], [%1], 16;" :: "r"(sa), "l"(g));
}

__device__ __forceinline__ void load_stage(uint32_t sbase, int m0, int n0,
                                           int k0, int K, int tid) {
    const __half* srcs[4] = {g_xh, g_xl, g_wh, g_wl};
    int r0s[4] = {m0, m0, n0, n0};
#pragma unroll
    for (int mat = 0; mat < 4; mat++) {
        const __half* src = srcs[mat];
        int r0 = r0s[mat];
#pragma unroll
        for (int s = 0; s < 2; s++) {
            int idx = tid * 2 + s;
            int row = idx >> 2, seg = idx & 3;
            const __half* g = src + (size_t)(r0 + row) * K + k0 + seg * 8;
            cpasync16(swz64(sbase + mat * MAT_BYTES, row, seg * 16), g);
        }
    }
}

__global__ __launch_bounds__(256, 2)
void hgemm_kernel(int M, int N, int K) {
    extern __shared__ __align__(1024) char smem[];
    const uint32_t sb = smem_u32(smem);
    const int tid = threadIdx.x;
    const int wid = tid >> 5, lane = tid & 31;
    const int wm = (wid & 1) * 64;
    const int wn = (wid >> 1) * 32;
    const int m0 = blockIdx.x * 128;
    const int n0 = blockIdx.y * 128;
    const int grp = lane >> 3, lr = lane & 7;
    const int NK = K / BKH;

    float acc[4][4][4];
#pragma unroll
    for (int i = 0; i < 4; i++)
#pragma unroll
        for (int j = 0; j < 4; j++)
#pragma unroll
            for (int q = 0; q < 4; q++) acc[i][j][q] = 0.f;

#pragma unroll
    for (int s = 0; s < STAGES - 1; s++) {
        load_stage(sb + s * STAGE_BYTES, m0, n0, s * BKH, K, tid);
        asm volatile("cp.async.commit_group;");
    }

    for (int ch = 0; ch < NK; ch++) {
        asm volatile("cp.async.wait_group %0;" :: "n"(STAGES - 2));
        __syncthreads();

        int pf = ch + STAGES - 1;
        if (pf < NK)
            load_stage(sb + (pf % STAGES) * STAGE_BYTES, m0, n0, pf * BKH, K, tid);
        asm volatile("cp.async.commit_group;");

        uint32_t sa = sb + (ch % STAGES) * STAGE_BYTES;
        uint32_t aH = sa, aL = sa + MAT_BYTES;
        uint32_t bH = sa + 2 * MAT_BYTES, bL = sa + 3 * MAT_BYTES;

#pragma unroll
        for (int ks = 0; ks < 2; ks++) {
            int kb = ks * 32;
            uint32_t Bh[4][2], Bl[4][2];
#pragma unroll
            for (int np = 0; np < 2; np++) {
                int nrow = wn + np * 16 + (grp >> 1) * 8 + lr;
                int kbyte = kb + (grp & 1) * 16;
                uint32_t r0, r1, r2, r3;
                LDSM4(r0, r1, r2, r3, swz64(bH, nrow, kbyte));
                Bh[np * 2][0] = r0; Bh[np * 2][1] = r1;
                Bh[np * 2 + 1][0] = r2; Bh[np * 2 + 1][1] = r3;
                LDSM4(r0, r1, r2, r3, swz64(bL, nrow, kbyte));
                Bl[np * 2][0] = r0; Bl[np * 2][1] = r1;
                Bl[np * 2 + 1][0] = r2; Bl[np * 2 + 1][1] = r3;
            }
#pragma unroll
            for (int mi = 0; mi < 4; mi++) {
                int arow = wm + mi * 16 + (grp & 1) * 8 + lr;
                int kbyte = kb + (grp >> 1) * 16;
                uint32_t a0, a1, a2, a3, l0, l1, l2, l3;
                LDSM4(a0, a1, a2, a3, swz64(aH, arow, kbyte));
                LDSM4(l0, l1, l2, l3, swz64(aL, arow, kbyte));
#pragma unroll
                for (int ni = 0; ni < 4; ni++)
                    MMA16816(acc[mi][ni], a0, a1, a2, a3, Bh[ni][0], Bh[ni][1]);
#pragma unroll
                for (int ni = 0; ni < 4; ni++)
                    MMA16816(acc[mi][ni], a0, a1, a2, a3, Bl[ni][0], Bl[ni][1]);
#pragma unroll
                for (int ni = 0; ni < 4; ni++)
                    MMA16816(acc[mi][ni], l0, l1, l2, l3, Bh[ni][0], Bh[ni][1]);
            }
        }
        __syncthreads();
    }

    // ---- epilogue: h16 store + fused column stats partials (FP64) ----
    const float sc = 9.313225746154785e-10f;  // 2^-30
    int gid = lane >> 2, tig = lane & 3;
#pragma unroll
    for (int mi = 0; mi < 4; mi++) {
#pragma unroll
        for (int ni = 0; ni < 4; ni++) {
            int r = m0 + wm + mi * 16 + gid;
            int c = n0 + wn + ni * 8 + tig * 2;
            *(__half2*)&g_h16[(size_t)r * N + c] =
                __floats2half2_rn(acc[mi][ni][0] * sc, acc[mi][ni][1] * sc);
            *(__half2*)&g_h16[(size_t)(r + 8) * N + c] =
                __floats2half2_rn(acc[mi][ni][2] * sc, acc[mi][ni][3] * sc);
        }
    }

    double csum[4][2], csq[4][2];
#pragma unroll
    for (int ni = 0; ni < 4; ni++)
#pragma unroll
        for (int qc = 0; qc < 2; qc++) {
            double s = 0.0, q = 0.0;
#pragma unroll
            for (int mi = 0; mi < 4; mi++) {
                double v1 = (double)(acc[mi][ni][qc]) * (double)sc;
                double v2 = (double)(acc[mi][ni][qc + 2]) * (double)sc;
                s += v1 + v2;
                q += v1 * v1 + v2 * v2;
            }
            csum[ni][qc] = s; csq[ni][qc] = q;
        }
#pragma unroll
    for (int off = 4; off <= 16; off <<= 1) {
#pragma unroll
        for (int ni = 0; ni < 4; ni++)
#pragma unroll
            for (int qc = 0; qc < 2; qc++) {
                csum[ni][qc] += __shfl_xor_sync(0xffffffffu, csum[ni][qc], off);
                csq[ni][qc]  += __shfl_xor_sync(0xffffffffu, csq[ni][qc], off);
            }
    }
    __syncthreads();
    double* scs = (double*)smem;     // [2][128]
    double* scq = scs + 256;
    if (gid == 0) {
#pragma unroll
        for (int ni = 0; ni < 4; ni++)
#pragma unroll
            for (int qc = 0; qc < 2; qc++) {
                int cl = wn + ni * 8 + tig * 2 + qc;
                scs[(wid & 1) * 128 + cl] = csum[ni][qc];
                scq[(wid & 1) * 128 + cl] = csq[ni][qc];
            }
    }
    __syncthreads();
    if (tid < 128) {
        int mt = blockIdx.x;
        g_psum[(size_t)mt * N + n0 + tid]   = scs[tid] + scs[128 + tid];
        g_psumsq[(size_t)mt * N + n0 + tid] = scq[tid] + scq[128 + tid];
    }
}

// ---------------------------------------------------------------------------
// Column stats finalize
// ---------------------------------------------------------------------------
__global__ void stats_final_kernel(const float* __restrict__ gamma,
                                   const float* __restrict__ beta,
                                   int Bsz, int C, int nslot) {
    int c = blockIdx.x * blockDim.x + threadIdx.x;
    if (c >= C) return;
    double s = 0, q = 0;
    for (int i = 0; i < nslot; i++) {
        s += g_psum[(size_t)i * C + c];
        q += g_psumsq[(size_t)i * C + c];
    }
    double mean = s / (double)Bsz;
    double var = q / (double)Bsz - mean * mean;
    double inv = 1.0 / sqrt(var + 1e-5);
    float sc = (float)((double)gamma[c] * inv);
    g_scale[c] = sc;
    g_bias[c] = beta[c] - (float)mean * sc;
}

// ---------------------------------------------------------------------------
// topk_select: BN+ReLU(h16) -> radix top-(k+16) -> candidate list to global.
// One 256-thread block per row; 74KB smem.
// ---------------------------------------------------------------------------
__global__ __launch_bounds__(256) void topk_select_kernel(
    const int* __restrict__ topk_p, int C) {
    extern __shared__ float sm[];
    float* vals = sm;                          // C floats
    unsigned* hist = (unsigned*)(vals + C);    // 2048
    unsigned* chunks = hist + 2048;            // 256

    __shared__ int s_selIdx[NCAND];
    __shared__ int s_eqIdx[256];
    __shared__ int s_nsel, s_neq, s_need, s_chunk, s_flagzero;
    __shared__ unsigned s_prefix;

    int row = blockIdx.x;
    int tid = threadIdx.x;
    int k = *topk_p;
    if (k > C) k = C;
    if (k > 128) k = 128;
    int kc = k + 16;
    if (kc > C) kc = C;
    if (kc > NCAND) kc = NCAND;

    for (int c = tid; c < C; c += 256) {
        float v = __half2float(g_h16[(size_t)row * C + c]);
        v = v * g_scale[c] + g_bias[c];
        vals[c] = (v > 0.f) ? v : 0.f;
    }
    if (tid == 0) { s_nsel = 0; s_neq = 0; s_need = kc; s_prefix = 0u; s_flagzero = 0; }
    __syncthreads();

    {
        const int shifts[3] = {21, 10, 0};
        const int nbitsA[3] = {11, 11, 10};
        const unsigned maskHi[3] = {0u, 0xFFE00000u, 0xFFFFFC00u};

        for (int r = 0; r < 3; r++) {
            int nb = 1 << nbitsA[r];
            for (int i = tid; i < nb; i += 256) hist[i] = 0u;
            __syncthreads();

            unsigned pre = s_prefix, mh = maskHi[r], msk = (unsigned)(nb - 1);
            int sh = shifts[r];
            for (int c = tid; c < C; c += 256) {
                unsigned key = __float_as_uint(vals[c]);
                if (key != 0u && (key & mh) == pre)
                    atomicAdd(&hist[(key >> sh) & msk], 1u);
            }
            __syncthreads();

            int NCH = nb >> 3;
            unsigned csum = 0u;
            if (tid < NCH) {
#pragma unroll
                for (int j = 0; j < 8; j++) csum += hist[tid * 8 + j];
                chunks[tid] = csum;
            }
            __syncthreads();
            for (int off = 1; off < NCH; off <<= 1) {
                unsigned add = 0u;
                if (tid < NCH && tid + off < NCH) add = chunks[tid + off];
                __syncthreads();
                if (tid < NCH) chunks[tid] += add;
                __syncthreads();
            }

            int need = s_need;
            if (tid < NCH) {
                int incl = (int)chunks[tid];
                int excl = incl - (int)csum;
                if (excl < need && incl >= need) s_chunk = tid;
                if (tid == 0 && incl < need) s_flagzero = 1;
            }
            __syncthreads();
            if (s_flagzero) break;

            if (tid == 0) {
                int t = s_chunk;
                unsigned cs = 0u;
#pragma unroll
                for (int j = 0; j < 8; j++) cs += hist[t * 8 + j];
                int cum = (int)chunks[t] - (int)cs;
                for (int j = 7; j >= 0; j--) {
                    int hc = (int)hist[t * 8 + j];
                    cum += hc;
                    if (cum >= need) {
                        s_prefix |= ((unsigned)(t * 8 + j)) << sh;
                        s_need = need - (cum - hc);
                        break;
                    }
                }
            }
            __syncthreads();
        }
        __syncthreads();

        unsigned T = s_prefix;
        int need_eq = s_need;
        bool zeroThresh = (s_flagzero != 0);

        for (int c = tid; c < C; c += 256) {
            unsigned key = __float_as_uint(vals[c]);
            if (key == 0u) continue;
            if (zeroThresh || key > T) {
                int p = atomicAdd(&s_nsel, 1);
                if (p < NCAND) s_selIdx[p] = c;
            } else if (key == T) {
                int p = atomicAdd(&s_neq, 1);
                if (p < 256) s_eqIdx[p] = c;
            }
        }
        __syncthreads();

        if (!zeroThresh && tid == 0) {
            int ne = s_neq; if (ne > 256) ne = 256;
            for (int i = 1; i < ne; i++) {
                int v = s_eqIdx[i]; int j = i - 1;
                while (j >= 0 && s_eqIdx[j] > v) { s_eqIdx[j + 1] = s_eqIdx[j]; j--; }
                s_eqIdx[j + 1] = v;
            }
            int take = need_eq; if (take > ne) take = ne;
            int base = s_nsel;
            for (int i = 0; i < take; i++) {
                int p = base + i;
                if (p < NCAND) s_selIdx[p] = s_eqIdx[i];
            }
            s_nsel = base + take;
        }
        __syncthreads();
    }

    int ncand = s_nsel; if (ncand > NCAND) ncand = NCAND;
    if (tid < ncand) g_candIdx[(size_t)row * NCAND + tid] = s_selIdx[tid];
    if (tid == 0) g_candCnt[row] = ncand;
}

// ---------------------------------------------------------------------------
// refine_decode: serial ascending-k fp32 FMA refinement of candidates
// (proven arithmetic), exact rank, sparse decode. ~12KB smem -> high occ.
// ---------------------------------------------------------------------------
__global__ __launch_bounds__(256) void refine_decode_kernel(
    const float* __restrict__ x, const float* __restrict__ W_enc,
    const float* __restrict__ b_dec, const int* __restrict__ topk_p,
    float* __restrict__ out, int C, int D) {
    __shared__ float xrow[MAX_D];
    __shared__ int s_idx[NCAND];
    __shared__ float s_val[NCAND];
    __shared__ int s_fIdx[128];
    __shared__ float s_fVal[128];

    int row = blockIdx.x;
    int tid = threadIdx.x;
    int k = *topk_p;
    if (k > C) k = C;
    if (k > 128) k = 128;

    int ncand = g_candCnt[row];
    if (ncand > NCAND) ncand = NCAND;
    if (tid < ncand) s_idx[tid] = g_candIdx[(size_t)row * NCAND + tid];
    for (int d = tid; d < D; d += 256) xrow[d] = x[(size_t)row * D + d];
    __syncthreads();

    int myc = (tid < ncand) ? s_idx[tid] : -1;

    // exact serial ascending-k FMA chain (identical facc sequence to R1/R4/R6/R9)
    if (myc >= 0) {
        const float4* wr = (const float4*)(W_enc + (size_t)myc * D);
        const int NIT = D >> 2;
        float facc = 0.f;
#pragma unroll 4
        for (int i = 0; i < NIT; i++) {
            float4 w = wr[i];
            const float* xq = &xrow[i << 2];
            facc = __fmaf_rn(xq[0], w.x, facc);
            facc = __fmaf_rn(xq[1], w.y, facc);
            facc = __fmaf_rn(xq[2], w.z, facc);
            facc = __fmaf_rn(xq[3], w.w, facc);
        }
        float bn = __fmaf_rn(facc, g_scale[myc], g_bias[myc]);
        s_val[tid] = (bn > 0.f) ? bn : 0.f;
    }
    __syncthreads();

    // exact rank (value desc, index asc)
    int kk = (k < ncand) ? k : ncand;
    if (tid < ncand) {
        float vj = s_val[tid]; int cj = myc;
        int rank = 0;
        for (int i = 0; i < ncand; i++) {
            float vi = s_val[i]; int ci = s_idx[i];
            if (vi > vj || (vi == vj && ci < cj)) rank++;
        }
        if (rank < kk) { s_fVal[rank] = vj; s_fIdx[rank] = cj; }
    }
    __syncthreads();

    // sparse decode
    for (int dbase = 0; dbase < D; dbase += 1024) {
        int d = dbase + tid * 4;
        if (d + 3 < D) {
            float4 acc = *(const float4*)(b_dec + d);
            for (int j = 0; j < kk; j++) {
                int ci = s_fIdx[j];
                float v = s_fVal[j];
                float4 w = *(const float4*)(&g_WnT[(size_t)ci * D + d]);
                acc.x += v * w.x; acc.y += v * w.y;
                acc.z += v * w.z; acc.w += v * w.w;
            }
            *(float4*)(out + (size_t)row * D + d) = acc;
        }
    }
}

// ---------------------------------------------------------------------------
// Launch — topk_select at slot #4 (ncu captures #4)
// ---------------------------------------------------------------------------
extern "C" void kernel_launch(void* const* d_in, const int* in_sizes, int n_in,
                              void* d_out, int out_size) {
    const float* x = (const float*)d_in[0];
    const float* W_enc = (const float*)d_in[1];
    const float* gamma = (const float*)d_in[3];
    const float* beta = (const float*)d_in[4];
    const float* W_dec = (const float*)d_in[5];
    const float* b_dec = (const float*)d_in[6];
    const int* topk = (const int*)d_in[7];

    int D = in_sizes[6];          // K
    int C = in_sizes[2];          // N
    int B = in_sizes[0] / D;      // M
    float* out = (float*)d_out;

    int nx = B * D, nw = C * D;
    split_all_kernel<<<(nx + nw + 255) / 256, 256>>>(x, W_enc, nx, nw);  // #1

    cudaFuncSetAttribute(hgemm_kernel,
                         cudaFuncAttributeMaxDynamicSharedMemorySize, GEMM_SMEM);
    dim3 gg(B / 128, C / 128);
    hgemm_kernel<<<gg, 256, GEMM_SMEM>>>(B, C, D);                       // #2

    stats_final_kernel<<<(C + 255) / 256, 256>>>(gamma, beta, B, C, B / 128);  // #3

    size_t dynSel = (size_t)C * sizeof(float) + 2048 * sizeof(unsigned) + 256 * sizeof(unsigned);
    cudaFuncSetAttribute(topk_select_kernel,
                         cudaFuncAttributeMaxDynamicSharedMemorySize, (int)dynSel);
    topk_select_kernel<<<B, 256, dynSel>>>(topk, C);                     // #4 (profiled)

    colnorm_kernel<<<(C + 255) / 256, 256>>>(W_dec, D, C);               // #5

    dim3 tg((C + 31) / 32, (D + 31) / 32);
    transpose_kernel<<<tg, dim3(32, 8)>>>(W_dec, D, C);                  // #6

    refine_decode_kernel<<<B, 256>>>(x, W_enc, b_dec, topk, out, C, D);  // #7
}